// round 4
// baseline (speedup 1.0000x reference)
#include <cuda_runtime.h>
#include <cuda_bf16.h>
#include <cstdint>
#include <cstddef>

// Problem constants
#define BB   512
#define TT   128
#define DIN  128
#define DHID 256

// ---------------------------------------------------------------------------
// Scratch (device globals; no allocations allowed)
// ---------------------------------------------------------------------------
__device__ float g_xg [(size_t)BB * TT * 4 * DHID];  // 256 MB : xg buffer (reused per layer)
__device__ float g_seq[(size_t)BB * TT * DHID];      //  64 MB : e0 / d0 / d1 (reused)
__device__ float g_hT [(size_t)BB * DHID];           // final hidden of enc1
__device__ float g_xgd0[(size_t)BB * 4 * DIN];       // dec0 xg (constant over t)

// ---------------------------------------------------------------------------
// Helpers
// ---------------------------------------------------------------------------
__device__ __forceinline__ float sigf(float x) { return 1.0f / (1.0f + __expf(-x)); }

__device__ __forceinline__ uint32_t smem_u32(const void* p) {
    uint32_t a;
    asm("{ .reg .u64 t; cvta.to.shared.u64 t, %1; cvt.u32.u64 %0, t; }" : "=r"(a) : "l"(p));
    return a;
}
__device__ __forceinline__ uint32_t cl_rank() {
    uint32_t r; asm("mov.u32 %0, %%cluster_ctarank;" : "=r"(r)); return r;
}
__device__ __forceinline__ uint32_t mapa_u32(uint32_t addr, uint32_t rank) {
    uint32_t r;
    asm("mapa.shared::cluster.u32 %0, %1, %2;" : "=r"(r) : "r"(addr), "r"(rank));
    return r;
}
__device__ __forceinline__ void st_cluster_v4(uint32_t addr, float a, float b, float c, float d) {
    asm volatile("st.shared::cluster.v4.f32 [%0], {%1,%2,%3,%4};"
                 :: "r"(addr), "f"(a), "f"(b), "f"(c), "f"(d) : "memory");
}
#define CLUSTER_SYNC_() do { \
    asm volatile("barrier.cluster.arrive.aligned;" ::: "memory"); \
    asm volatile("barrier.cluster.wait.aligned;"   ::: "memory"); \
} while (0)

// ---------------------------------------------------------------------------
// Recurrent LSTM kernel.
//   Cluster of 8 CTAs per batch-tile of 32. CTA rank r owns hidden columns
//   [r*JC, r*JC+JC). Whh slice (rows {g*H + r*JC + cl}) lives in SMEM,
//   transposed to k-major. h (full H) is replicated per CTA, double-buffered;
//   each step every CTA broadcasts its new h-slice to all 8 peers via DSMEM,
//   then one cluster barrier.
//   xg layout: xg[(b0+b)*xg_b_stride + t*xg_t_stride + g*H + k]
// ---------------------------------------------------------------------------
template <int H>
__global__ void __cluster_dims__(8, 1, 1) __launch_bounds__(256, 1)
lstm_rec_kernel(const float* __restrict__ Whh,        // [4H][H]
                const float* __restrict__ xg,
                size_t xg_b_stride, int xg_t_stride,
                float* __restrict__ out_seq,           // [B][T][H] or null
                float* __restrict__ out_final)         // [B][H]    or null
{
    constexpr int K   = H;        // dot length
    constexpr int JC  = H / 8;    // hidden columns per CTA
    constexpr int GR  = 4 * JC;   // gate rows per CTA
    constexpr int JT  = GR / 32;  // j's per thread (4 for H=256, 2 for H=128)
    constexpr int HSS = 36;       // padded batch stride inside h_s rows
    constexpr int Bt  = 32;

    extern __shared__ float smem[];
    float* w_s = smem;                       // [K][GR]   k-major
    float* h_s = w_s + K * GR;               // [2][K][HSS]
    float* gsm = h_s + 2 * K * HSS;          // [GR][HSS] raw dots
    float* c_s = gsm + GR * HSS;             // [Bt][JC]

    const int tid = threadIdx.x;
    const uint32_t r = cl_rank();
    const int cid = blockIdx.x >> 3;
    const int b0  = cid * Bt;

    // ---- load Whh slice, transposed to w_s[k][j] -------------------------
    for (int idx = tid; idx < GR * K; idx += 256) {
        int j = idx / K, k = idx % K;             // consecutive tid -> consecutive k
        int g = j / JC, cl = j % JC;
        w_s[k * GR + j] = Whh[(size_t)(g * H + r * JC + cl) * K + k];
    }
    // ---- zero state ------------------------------------------------------
    for (int idx = tid; idx < 2 * K * HSS; idx += 256) h_s[idx] = 0.0f;
    for (int idx = tid; idx < Bt * JC;     idx += 256) c_s[idx] = 0.0f;
    __syncthreads();
    CLUSTER_SYNC_();

    const uint32_t sbase = smem_u32(smem);
    const uint32_t hs_byte = (uint32_t)(K * GR) * 4u;   // byte offset of h_s

    const int bg = tid >> 5;        // 0..7  -> batch quad (b = bg*4 .. +3)
    const int jg = tid & 31;        // 0..31 -> j group (j = jg*JT .. +JT-1)

    for (int t = 0; t < TT; ++t) {
        // ================= phase 1: dots ==================================
        const float* hb = h_s + (size_t)(t & 1) * (K * HSS);
        float acc[4][JT];
        #pragma unroll
        for (int bi = 0; bi < 4; ++bi)
            #pragma unroll
            for (int ji = 0; ji < JT; ++ji) acc[bi][ji] = 0.0f;

        #pragma unroll 4
        for (int k = 0; k < K; ++k) {
            float4 hv = *reinterpret_cast<const float4*>(hb + k * HSS + (bg << 2));
            float wv[JT];
            if constexpr (JT == 4) {
                float4 w4 = *reinterpret_cast<const float4*>(w_s + k * GR + (jg << 2));
                wv[0] = w4.x; wv[1] = w4.y; wv[2] = w4.z; wv[3] = w4.w;
            } else {
                float2 w2 = *reinterpret_cast<const float2*>(w_s + k * GR + (jg << 1));
                wv[0] = w2.x; wv[1] = w2.y;
            }
            float hvv[4] = {hv.x, hv.y, hv.z, hv.w};
            #pragma unroll
            for (int bi = 0; bi < 4; ++bi)
                #pragma unroll
                for (int ji = 0; ji < JT; ++ji)
                    acc[bi][ji] += hvv[bi] * wv[ji];
        }
        #pragma unroll
        for (int ji = 0; ji < JT; ++ji) {
            float4 v = make_float4(acc[0][ji], acc[1][ji], acc[2][ji], acc[3][ji]);
            *reinterpret_cast<float4*>(gsm + (jg * JT + ji) * HSS + (bg << 2)) = v;
        }
        __syncthreads();

        // ================= phase 2: gates + state + broadcast =============
        const float* xgt = xg + (size_t)t * xg_t_stride;
        const int items = 8 * JC;                 // quads of batch
        for (int it = tid; it < items; it += 256) {
            int cl = it % JC;
            int bq = it / JC;
            int bb = bq << 2;
            int kk = r * JC + cl;

            float hq[4];
            #pragma unroll
            for (int q = 0; q < 4; ++q) {
                int b = bb + q;
                size_t bo = (size_t)(b0 + b) * xg_b_stride + kk;
                float gi = gsm[(0 * JC + cl) * HSS + b] + xgt[bo + 0 * H];
                float gf = gsm[(1 * JC + cl) * HSS + b] + xgt[bo + 1 * H];
                float gg = gsm[(2 * JC + cl) * HSS + b] + xgt[bo + 2 * H];
                float go = gsm[(3 * JC + cl) * HSS + b] + xgt[bo + 3 * H];
                float i_ = sigf(gi), f_ = sigf(gf), o_ = sigf(go);
                float g_ = tanhf(gg);
                float c  = f_ * c_s[b * JC + cl] + i_ * g_;
                c_s[b * JC + cl] = c;
                float h  = o_ * tanhf(c);
                hq[q] = h;
                if (out_seq)
                    out_seq[((size_t)(b0 + b) * TT + t) * H + kk] = h;
            }
            // broadcast h quad to all 8 peers' next h buffer
            uint32_t loff = sbase + hs_byte +
                (uint32_t)(((((t + 1) & 1) * K + kk) * HSS + bb) * 4);
            #pragma unroll
            for (int p = 0; p < 8; ++p) {
                uint32_t ra = mapa_u32(loff, (uint32_t)p);
                st_cluster_v4(ra, hq[0], hq[1], hq[2], hq[3]);
            }
        }
        __syncthreads();
        CLUSTER_SYNC_();
    }

    if (out_final) {
        const float* hf = h_s + (size_t)(TT & 1) * (K * HSS);
        for (int idx = tid; idx < Bt * JC; idx += 256) {
            int cl = idx % JC, b = idx / JC;
            out_final[(size_t)(b0 + b) * H + r * JC + cl] = hf[(r * JC + cl) * HSS + b];
        }
    }
}

// ---------------------------------------------------------------------------
// SGEMM with fused bias: C[m][n] = sum_k A[m][k]*B[n][k] + b1[n] (+ b2[n])
// BM=128 BN=64 BK=16, 256 threads, 8x4 micro-tile.
// ---------------------------------------------------------------------------
__global__ __launch_bounds__(256) void sgemm_bias_kernel(
    const float* __restrict__ A, const float* __restrict__ B,
    const float* __restrict__ b1, const float* __restrict__ b2,
    float* __restrict__ C, int M, int N, int K)
{
    __shared__ float As[16][132];
    __shared__ float Bs[16][68];

    const int tid = threadIdx.x;
    const int bm = blockIdx.y * 128;
    const int bn = blockIdx.x * 64;
    const int tx = tid & 15;         // n group
    const int ty = tid >> 4;         // m group
    const int lrow = tid >> 2;       // 0..63
    const int lcol = (tid & 3) << 2; // 0,4,8,12

    float acc[8][4];
    #pragma unroll
    for (int i = 0; i < 8; ++i)
        #pragma unroll
        for (int j = 0; j < 4; ++j) acc[i][j] = 0.0f;

    const float* Ap0 = A + (size_t)(bm + lrow) * K + lcol;
    const float* Ap1 = A + (size_t)(bm + lrow + 64) * K + lcol;
    const float* Bp  = B + (size_t)(bn + lrow) * K + lcol;

    for (int k0 = 0; k0 < K; k0 += 16) {
        float4 a0 = *reinterpret_cast<const float4*>(Ap0 + k0);
        float4 a1 = *reinterpret_cast<const float4*>(Ap1 + k0);
        float4 bv = *reinterpret_cast<const float4*>(Bp + k0);
        As[lcol + 0][lrow]      = a0.x; As[lcol + 1][lrow]      = a0.y;
        As[lcol + 2][lrow]      = a0.z; As[lcol + 3][lrow]      = a0.w;
        As[lcol + 0][lrow + 64] = a1.x; As[lcol + 1][lrow + 64] = a1.y;
        As[lcol + 2][lrow + 64] = a1.z; As[lcol + 3][lrow + 64] = a1.w;
        Bs[lcol + 0][lrow] = bv.x; Bs[lcol + 1][lrow] = bv.y;
        Bs[lcol + 2][lrow] = bv.z; Bs[lcol + 3][lrow] = bv.w;
        __syncthreads();

        #pragma unroll
        for (int k = 0; k < 16; ++k) {
            float av[8], bw[4];
            *reinterpret_cast<float4*>(av)     = *reinterpret_cast<const float4*>(&As[k][ty * 8]);
            *reinterpret_cast<float4*>(av + 4) = *reinterpret_cast<const float4*>(&As[k][ty * 8 + 4]);
            *reinterpret_cast<float4*>(bw)     = *reinterpret_cast<const float4*>(&Bs[k][tx * 4]);
            #pragma unroll
            for (int i = 0; i < 8; ++i)
                #pragma unroll
                for (int j = 0; j < 4; ++j)
                    acc[i][j] += av[i] * bw[j];
        }
        __syncthreads();
    }

    float bias[4];
    #pragma unroll
    for (int j = 0; j < 4; ++j) {
        int n = bn + tx * 4 + j;
        bias[j] = b1[n] + (b2 ? b2[n] : 0.0f);
    }
    #pragma unroll
    for (int i = 0; i < 8; ++i) {
        float4 o = make_float4(acc[i][0] + bias[0], acc[i][1] + bias[1],
                               acc[i][2] + bias[2], acc[i][3] + bias[3]);
        *reinterpret_cast<float4*>(C + (size_t)(bm + ty * 8 + i) * N + bn + tx * 4) = o;
    }
}

// ---------------------------------------------------------------------------
// Launch
// ---------------------------------------------------------------------------
static const int SMEM_REC256 = (DHID * DHID / 2 + 94 * DHID) * 4;  // 227328 B
static const int SMEM_REC128 = (DIN  * DIN  / 2 + 94 * DIN ) * 4;  //  80896 B

extern "C" void kernel_launch(void* const* d_in, const int* in_sizes, int n_in,
                              void* d_out, int out_size)
{
    (void)in_sizes; (void)n_in; (void)out_size;
    const float* x        = (const float*)d_in[0];
    const float* e0_Wih   = (const float*)d_in[1];
    const float* e0_Whh   = (const float*)d_in[2];
    const float* e0_bih   = (const float*)d_in[3];
    const float* e0_bhh   = (const float*)d_in[4];
    const float* e1_Wih   = (const float*)d_in[5];
    const float* e1_Whh   = (const float*)d_in[6];
    const float* e1_bih   = (const float*)d_in[7];
    const float* e1_bhh   = (const float*)d_in[8];
    const float* d0_Wih   = (const float*)d_in[9];
    const float* d0_Whh   = (const float*)d_in[10];
    const float* d0_bih   = (const float*)d_in[11];
    const float* d0_bhh   = (const float*)d_in[12];
    const float* d1_Wih   = (const float*)d_in[13];
    const float* d1_Whh   = (const float*)d_in[14];
    const float* d1_bih   = (const float*)d_in[15];
    const float* d1_bhh   = (const float*)d_in[16];
    const float* out_W    = (const float*)d_in[17];
    const float* out_b    = (const float*)d_in[18];
    float* out = (float*)d_out;

    float *xg, *seq, *hT, *xgd0;
    cudaGetSymbolAddress((void**)&xg,   g_xg);
    cudaGetSymbolAddress((void**)&seq,  g_seq);
    cudaGetSymbolAddress((void**)&hT,   g_hT);
    cudaGetSymbolAddress((void**)&xgd0, g_xgd0);

    cudaFuncSetAttribute(lstm_rec_kernel<DHID>,
                         cudaFuncAttributeMaxDynamicSharedMemorySize, SMEM_REC256);
    cudaFuncSetAttribute(lstm_rec_kernel<DIN>,
                         cudaFuncAttributeMaxDynamicSharedMemorySize, SMEM_REC128);

    const int MT = BB * TT;  // 65536

    // 1) xg0 = x @ enc0_Wih^T + b   [65536, 1024]
    sgemm_bias_kernel<<<dim3(4 * DHID / 64, MT / 128), 256>>>(
        x, e0_Wih, e0_bih, e0_bhh, xg, MT, 4 * DHID, DIN);

    // 2) enc0 recurrence -> e0 (seq)
    lstm_rec_kernel<DHID><<<128, 256, SMEM_REC256>>>(
        e0_Whh, xg, (size_t)TT * 4 * DHID, 4 * DHID, seq, nullptr);

    // 3) xg1 = e0 @ enc1_Wih^T + b   [65536, 1024]
    sgemm_bias_kernel<<<dim3(4 * DHID / 64, MT / 128), 256>>>(
        seq, e1_Wih, e1_bih, e1_bhh, xg, MT, 4 * DHID, DHID);

    // 4) enc1 recurrence -> hT only
    lstm_rec_kernel<DHID><<<128, 256, SMEM_REC256>>>(
        e1_Whh, xg, (size_t)TT * 4 * DHID, 4 * DHID, nullptr, hT);

    // 5) dec0 xg (constant over t): hT @ dec0_Wih^T + b   [512, 512]
    sgemm_bias_kernel<<<dim3(4 * DIN / 64, BB / 128), 256>>>(
        hT, d0_Wih, d0_bih, d0_bhh, xgd0, BB, 4 * DIN, DHID);

    // 6) dec0 recurrence (t-stride 0) -> d0 (seq)
    lstm_rec_kernel<DIN><<<128, 256, SMEM_REC128>>>(
        d0_Whh, xgd0, (size_t)4 * DIN, 0, seq, nullptr);

    // 7) xgd1 = d0 @ dec1_Wih^T + b   [65536, 512]
    sgemm_bias_kernel<<<dim3(4 * DIN / 64, MT / 128), 256>>>(
        seq, d1_Wih, d1_bih, d1_bhh, xg, MT, 4 * DIN, DIN);

    // 8) dec1 recurrence -> d1 (seq, overwrites d0; only xg is read)
    lstm_rec_kernel<DIN><<<128, 256, SMEM_REC128>>>(
        d1_Whh, xg, (size_t)TT * 4 * DIN, 4 * DIN, seq, nullptr);

    // 9) out = d1 @ out_W^T + out_b   [65536, 128]
    sgemm_bias_kernel<<<dim3(DIN / 64, MT / 128), 256>>>(
        seq, out_W, out_b, nullptr, out, MT, DIN, DIN);
}

// round 5
// speedup vs baseline: 1.3616x; 1.3616x over previous
#include <cuda_runtime.h>
#include <cuda_bf16.h>
#include <cstdint>
#include <cstddef>

#define BB   512
#define TT   128
#define DIN  128
#define DHID 256

// ---------------------------------------------------------------------------
// Scratch (device globals; no allocations allowed)
// ---------------------------------------------------------------------------
__device__ float g_xg [(size_t)BB * TT * 4 * DHID];
__device__ float g_seq[(size_t)BB * TT * DHID];
__device__ float g_hT [(size_t)BB * DHID];
__device__ float g_xgd0[(size_t)BB * 4 * DIN];

// ---------------------------------------------------------------------------
// Helpers
// ---------------------------------------------------------------------------
__device__ __forceinline__ float sigf(float x) { return 1.0f / (1.0f + __expf(-x)); }
__device__ __forceinline__ float tanhe(float x) {
    x = fminf(fmaxf(x, -15.0f), 15.0f);
    float e = __expf(-2.0f * x);
    return __fdividef(1.0f - e, 1.0f + e);
}
__device__ __forceinline__ uint32_t f2tf32(float x) {
    uint32_t u; asm("cvt.rna.tf32.f32 %0, %1;" : "=r"(u) : "f"(x)); return u;
}
__device__ __forceinline__ uint32_t smem_u32(const void* p) {
    uint32_t a;
    asm("{ .reg .u64 t; cvta.to.shared.u64 t, %1; cvt.u32.u64 %0, t; }" : "=r"(a) : "l"(p));
    return a;
}
__device__ __forceinline__ uint32_t cl_rank() {
    uint32_t r; asm("mov.u32 %0, %%cluster_ctarank;" : "=r"(r)); return r;
}
__device__ __forceinline__ uint32_t mapa_u32(uint32_t addr, uint32_t rank) {
    uint32_t r;
    asm("mapa.shared::cluster.u32 %0, %1, %2;" : "=r"(r) : "r"(addr), "r"(rank));
    return r;
}
__device__ __forceinline__ void st_cluster_v4(uint32_t addr, float a, float b, float c, float d) {
    asm volatile("st.shared::cluster.v4.f32 [%0], {%1,%2,%3,%4};"
                 :: "r"(addr), "f"(a), "f"(b), "f"(c), "f"(d) : "memory");
}
#define CLUSTER_SYNC_() do { \
    asm volatile("barrier.cluster.arrive.aligned;" ::: "memory"); \
    asm volatile("barrier.cluster.wait.aligned;"   ::: "memory"); \
} while (0)

__device__ __forceinline__ void mma_tf32(float4& c, const uint32_t a[4],
                                         uint32_t b0, uint32_t b1) {
    asm volatile(
        "mma.sync.aligned.m16n8k8.row.col.f32.tf32.tf32.f32 "
        "{%0,%1,%2,%3}, {%4,%5,%6,%7}, {%8,%9}, {%0,%1,%2,%3};"
        : "+f"(c.x), "+f"(c.y), "+f"(c.z), "+f"(c.w)
        : "r"(a[0]), "r"(a[1]), "r"(a[2]), "r"(a[3]), "r"(b0), "r"(b1));
}

// ---------------------------------------------------------------------------
// Recurrent LSTM, tensor-core edition.
// Cluster of 8 CTAs per batch-tile of 32; rank r owns gate rows
// {g*H + r*JC + cl}. Whh slice lives in REGISTERS as tf32 A fragments
// (warp = (m-tile, k-slice); KH k-slices). h (full H, fp32) replicated per
// CTA (double-buffered); phase 1.5 splits it once into tf32 hi/lo SMEM
// buffers; phase 1 does 2 MMAs per tile (A*hi + A*lo) => h path is exact,
// only Whh carries one static tf32 rounding. Phase 2 computes gates (cell
// state in registers) and broadcasts the new h slice to all 8 peers (DSMEM).
// ---------------------------------------------------------------------------
template <int H, int KH>
__global__ void __cluster_dims__(8, 1, 1) __launch_bounds__(512, 1)
lstm_rec_mma(const float* __restrict__ Whh,        // [4H][H]
             const float* __restrict__ xg,
             size_t xg_b_stride, int xg_t_stride,
             float* __restrict__ out_seq,           // [B][T][H] or null
             float* __restrict__ out_final)         // [B][H]    or null
{
    constexpr int K   = H;
    constexpr int JC  = H / 8;          // hidden cols per CTA rank
    constexpr int GR  = 4 * JC;         // gate rows per CTA
    constexpr int KT  = (K / 8) / KH;   // k-tiles per warp (enc 16, dec 4)
    constexpr int SH  = K + 4;          // h row stride -> conflict-free banks
    constexpr int SG  = 36;             // gsm row stride
    constexpr int Bt  = 32;
    constexpr int HS_TOT = 2 * Bt * SH;

    extern __shared__ float smem[];
    float* h_s  = smem;                  // [2][Bt][SH] fp32 (remote writes land here)
    float* hi_s = h_s + HS_TOT;          // [Bt][SH] tf32(h)
    float* lo_s = hi_s + Bt * SH;        // [Bt][SH] tf32(h - hi)
    float* gsm  = lo_s + Bt * SH;        // [KH][GR][SG]

    const int tid  = threadIdx.x;
    const int wid  = tid >> 5;
    const int lane = tid & 31;
    const int gid  = lane >> 2;   // 0..7
    const int tk   = lane & 3;    // 0..3
    const uint32_t r = cl_rank();
    const int b0 = (blockIdx.x >> 3) * Bt;

    const int mt = wid / KH;             // m-tile (16 gate rows)
    const int kh = wid % KH;             // k-slice
    const int m0 = mt * 16;
    const int kbase = kh * (KT * 8);

    // zero h (both buffers, incl. padding)
    for (int i = tid; i < HS_TOT; i += 512) h_s[i] = 0.0f;

    // ---- preload A fragments (tf32 in registers) -------------------------
    uint32_t A[KT][4];
    {
        int j1 = m0 + gid, j2 = j1 + 8;
        const float* w1 = Whh + (size_t)((j1 / JC) * H + r * JC + (j1 % JC)) * K;
        const float* w2 = Whh + (size_t)((j2 / JC) * H + r * JC + (j2 % JC)) * K;
        #pragma unroll
        for (int kt = 0; kt < KT; ++kt) {
            int k0 = kbase + kt * 8 + tk;
            A[kt][0] = f2tf32(w1[k0]);
            A[kt][1] = f2tf32(w2[k0]);
            A[kt][2] = f2tf32(w1[k0 + 4]);
            A[kt][3] = f2tf32(w2[k0 + 4]);
        }
    }
    __syncthreads();
    CLUSTER_SYNC_();

    const uint32_t sbase = smem_u32(smem);
    const int kk0_r = r * JC;
    float cv[4] = {0.0f, 0.0f, 0.0f, 0.0f};   // persistent cell state (phase-2 owner)

    for (int t = 0; t < TT; ++t) {
        // ======== phase 1.5: split h (fp32) -> hi/lo (tf32) ===============
        {
            const float* hb = h_s + (t & 1) * (Bt * SH);
            constexpr int QUADS = Bt * (K / 4);
            for (int q = tid; q < QUADS; q += 512) {
                int b = q / (K / 4), kq = (q % (K / 4)) * 4;
                float4 v = *reinterpret_cast<const float4*>(hb + b * SH + kq);
                uint32_t h0 = f2tf32(v.x), h1 = f2tf32(v.y),
                         h2 = f2tf32(v.z), h3 = f2tf32(v.w);
                float4 hv = make_float4(__uint_as_float(h0), __uint_as_float(h1),
                                        __uint_as_float(h2), __uint_as_float(h3));
                float4 lv = make_float4(
                    __uint_as_float(f2tf32(v.x - hv.x)),
                    __uint_as_float(f2tf32(v.y - hv.y)),
                    __uint_as_float(f2tf32(v.z - hv.z)),
                    __uint_as_float(f2tf32(v.w - hv.w)));
                *reinterpret_cast<float4*>(hi_s + b * SH + kq) = hv;
                *reinterpret_cast<float4*>(lo_s + b * SH + kq) = lv;
            }
        }
        __syncthreads();

        // ======== phase 1: tensor-core dots ===============================
        {
            const float* hib = hi_s + gid * SH + kbase + tk;
            const float* lob = lo_s + gid * SH + kbase + tk;

            float4 C[4];
            #pragma unroll
            for (int nt = 0; nt < 4; ++nt) C[nt] = make_float4(0.f, 0.f, 0.f, 0.f);

            #pragma unroll
            for (int kt = 0; kt < KT; ++kt) {
                #pragma unroll
                for (int nt = 0; nt < 4; ++nt) {
                    int off = nt * 8 * SH + kt * 8;
                    uint32_t bh0 = __float_as_uint(hib[off]);
                    uint32_t bh1 = __float_as_uint(hib[off + 4]);
                    uint32_t bl0 = __float_as_uint(lob[off]);
                    uint32_t bl1 = __float_as_uint(lob[off + 4]);
                    mma_tf32(C[nt], A[kt], bh0, bh1);
                    mma_tf32(C[nt], A[kt], bl0, bl1);
                }
            }
            float* gout = gsm + kh * (GR * SG);
            #pragma unroll
            for (int nt = 0; nt < 4; ++nt) {
                int col = nt * 8 + 2 * tk;
                *reinterpret_cast<float2*>(&gout[(m0 + gid) * SG + col]) =
                    make_float2(C[nt].x, C[nt].y);
                *reinterpret_cast<float2*>(&gout[(m0 + gid + 8) * SG + col]) =
                    make_float2(C[nt].z, C[nt].w);
            }
        }
        __syncthreads();

        // ======== phase 2: gates + state + broadcast ======================
        constexpr int ITEMS = Bt * (JC / 4);
        if (tid < ITEMS) {
            int b   = tid & 31;
            int clq = tid >> 5;
            int cl0 = clq * 4;
            int kk0 = kk0_r + cl0;
            const float* xgt = xg + (size_t)t * xg_t_stride
                                  + (size_t)(b0 + b) * xg_b_stride + kk0;

            float4 xi = *reinterpret_cast<const float4*>(xgt);
            float4 xf = *reinterpret_cast<const float4*>(xgt + H);
            float4 xc = *reinterpret_cast<const float4*>(xgt + 2 * H);
            float4 xo = *reinterpret_cast<const float4*>(xgt + 3 * H);
            float gi[4] = {xi.x, xi.y, xi.z, xi.w};
            float gf[4] = {xf.x, xf.y, xf.z, xf.w};
            float gc[4] = {xc.x, xc.y, xc.z, xc.w};
            float go[4] = {xo.x, xo.y, xo.z, xo.w};

            float hv[4];
            #pragma unroll
            for (int q = 0; q < 4; ++q) {
                int row = cl0 + q;
                #pragma unroll
                for (int khx = 0; khx < KH; ++khx) {
                    const float* gp = gsm + khx * (GR * SG) + b;
                    gi[q] += gp[(0 * JC + row) * SG];
                    gf[q] += gp[(1 * JC + row) * SG];
                    gc[q] += gp[(2 * JC + row) * SG];
                    go[q] += gp[(3 * JC + row) * SG];
                }
                float i_ = sigf(gi[q]), f_ = sigf(gf[q]), o_ = sigf(go[q]);
                float g_ = tanhe(gc[q]);
                float c  = f_ * cv[q] + i_ * g_;
                cv[q] = c;
                hv[q] = o_ * tanhe(c);
            }
            if (out_seq)
                *reinterpret_cast<float4*>(
                    &out_seq[((size_t)(b0 + b) * TT + t) * H + kk0]) =
                    make_float4(hv[0], hv[1], hv[2], hv[3]);
            if (out_final && t == TT - 1)
                *reinterpret_cast<float4*>(
                    &out_final[(size_t)(b0 + b) * H + kk0]) =
                    make_float4(hv[0], hv[1], hv[2], hv[3]);

            uint32_t loff = sbase +
                (uint32_t)(((((t + 1) & 1) * Bt + b) * SH + kk0) * 4);
            #pragma unroll
            for (int p = 0; p < 8; ++p) {
                uint32_t ra = mapa_u32(loff, (uint32_t)p);
                st_cluster_v4(ra, hv[0], hv[1], hv[2], hv[3]);
            }
        }
        __syncthreads();
        CLUSTER_SYNC_();
    }
}

// ---------------------------------------------------------------------------
// SGEMM with fused bias: C[m][n] = sum_k A[m][k]*B[n][k] + b1[n] (+ b2[n])
// BM=128 BN=64 BK=16, 256 threads, 8x4 micro-tile.  (unchanged, proven)
// ---------------------------------------------------------------------------
__global__ __launch_bounds__(256) void sgemm_bias_kernel(
    const float* __restrict__ A, const float* __restrict__ B,
    const float* __restrict__ b1, const float* __restrict__ b2,
    float* __restrict__ C, int M, int N, int K)
{
    __shared__ float As[16][132];
    __shared__ float Bs[16][68];

    const int tid = threadIdx.x;
    const int bm = blockIdx.y * 128;
    const int bn = blockIdx.x * 64;
    const int tx = tid & 15;
    const int ty = tid >> 4;
    const int lrow = tid >> 2;
    const int lcol = (tid & 3) << 2;

    float acc[8][4];
    #pragma unroll
    for (int i = 0; i < 8; ++i)
        #pragma unroll
        for (int j = 0; j < 4; ++j) acc[i][j] = 0.0f;

    const float* Ap0 = A + (size_t)(bm + lrow) * K + lcol;
    const float* Ap1 = A + (size_t)(bm + lrow + 64) * K + lcol;
    const float* Bp  = B + (size_t)(bn + lrow) * K + lcol;

    for (int k0 = 0; k0 < K; k0 += 16) {
        float4 a0 = *reinterpret_cast<const float4*>(Ap0 + k0);
        float4 a1 = *reinterpret_cast<const float4*>(Ap1 + k0);
        float4 bv = *reinterpret_cast<const float4*>(Bp + k0);
        As[lcol + 0][lrow]      = a0.x; As[lcol + 1][lrow]      = a0.y;
        As[lcol + 2][lrow]      = a0.z; As[lcol + 3][lrow]      = a0.w;
        As[lcol + 0][lrow + 64] = a1.x; As[lcol + 1][lrow + 64] = a1.y;
        As[lcol + 2][lrow + 64] = a1.z; As[lcol + 3][lrow + 64] = a1.w;
        Bs[lcol + 0][lrow] = bv.x; Bs[lcol + 1][lrow] = bv.y;
        Bs[lcol + 2][lrow] = bv.z; Bs[lcol + 3][lrow] = bv.w;
        __syncthreads();

        #pragma unroll
        for (int k = 0; k < 16; ++k) {
            float av[8], bw[4];
            *reinterpret_cast<float4*>(av)     = *reinterpret_cast<const float4*>(&As[k][ty * 8]);
            *reinterpret_cast<float4*>(av + 4) = *reinterpret_cast<const float4*>(&As[k][ty * 8 + 4]);
            *reinterpret_cast<float4*>(bw)     = *reinterpret_cast<const float4*>(&Bs[k][tx * 4]);
            #pragma unroll
            for (int i = 0; i < 8; ++i)
                #pragma unroll
                for (int j = 0; j < 4; ++j)
                    acc[i][j] += av[i] * bw[j];
        }
        __syncthreads();
    }

    float bias[4];
    #pragma unroll
    for (int j = 0; j < 4; ++j) {
        int n = bn + tx * 4 + j;
        bias[j] = b1[n] + (b2 ? b2[n] : 0.0f);
    }
    #pragma unroll
    for (int i = 0; i < 8; ++i) {
        float4 o = make_float4(acc[i][0] + bias[0], acc[i][1] + bias[1],
                               acc[i][2] + bias[2], acc[i][3] + bias[3]);
        *reinterpret_cast<float4*>(C + (size_t)(bm + ty * 8 + i) * N + bn + tx * 4) = o;
    }
}

// ---------------------------------------------------------------------------
// Launch
// ---------------------------------------------------------------------------
static const int SMEM_ENC = (2 * 32 * (DHID + 4) + 2 * 32 * (DHID + 4)
                             + 2 * 4 * (DHID / 8) * 36) * 4;     // 169984 B
static const int SMEM_DEC = (2 * 32 * (DIN + 4) + 2 * 32 * (DIN + 4)
                             + 4 * 4 * (DIN / 8) * 36) * 4;      // 104448 B

extern "C" void kernel_launch(void* const* d_in, const int* in_sizes, int n_in,
                              void* d_out, int out_size)
{
    (void)in_sizes; (void)n_in; (void)out_size;
    const float* x        = (const float*)d_in[0];
    const float* e0_Wih   = (const float*)d_in[1];
    const float* e0_Whh   = (const float*)d_in[2];
    const float* e0_bih   = (const float*)d_in[3];
    const float* e0_bhh   = (const float*)d_in[4];
    const float* e1_Wih   = (const float*)d_in[5];
    const float* e1_Whh   = (const float*)d_in[6];
    const float* e1_bih   = (const float*)d_in[7];
    const float* e1_bhh   = (const float*)d_in[8];
    const float* d0_Wih   = (const float*)d_in[9];
    const float* d0_Whh   = (const float*)d_in[10];
    const float* d0_bih   = (const float*)d_in[11];
    const float* d0_bhh   = (const float*)d_in[12];
    const float* d1_Wih   = (const float*)d_in[13];
    const float* d1_Whh   = (const float*)d_in[14];
    const float* d1_bih   = (const float*)d_in[15];
    const float* d1_bhh   = (const float*)d_in[16];
    const float* out_W    = (const float*)d_in[17];
    const float* out_b    = (const float*)d_in[18];
    float* out = (float*)d_out;

    float *xg, *seq, *hT, *xgd0;
    cudaGetSymbolAddress((void**)&xg,   g_xg);
    cudaGetSymbolAddress((void**)&seq,  g_seq);
    cudaGetSymbolAddress((void**)&hT,   g_hT);
    cudaGetSymbolAddress((void**)&xgd0, g_xgd0);

    cudaFuncSetAttribute(lstm_rec_mma<DHID, 2>,
                         cudaFuncAttributeMaxDynamicSharedMemorySize, SMEM_ENC);
    cudaFuncSetAttribute(lstm_rec_mma<DIN, 4>,
                         cudaFuncAttributeMaxDynamicSharedMemorySize, SMEM_DEC);

    const int MT = BB * TT;  // 65536

    // 1) xg0 = x @ enc0_Wih^T + b   [65536, 1024]
    sgemm_bias_kernel<<<dim3(4 * DHID / 64, MT / 128), 256>>>(
        x, e0_Wih, e0_bih, e0_bhh, xg, MT, 4 * DHID, DIN);

    // 2) enc0 recurrence -> e0 (seq)
    lstm_rec_mma<DHID, 2><<<128, 512, SMEM_ENC>>>(
        e0_Whh, xg, (size_t)TT * 4 * DHID, 4 * DHID, seq, nullptr);

    // 3) xg1 = e0 @ enc1_Wih^T + b   [65536, 1024]
    sgemm_bias_kernel<<<dim3(4 * DHID / 64, MT / 128), 256>>>(
        seq, e1_Wih, e1_bih, e1_bhh, xg, MT, 4 * DHID, DHID);

    // 4) enc1 recurrence -> hT only
    lstm_rec_mma<DHID, 2><<<128, 512, SMEM_ENC>>>(
        e1_Whh, xg, (size_t)TT * 4 * DHID, 4 * DHID, nullptr, hT);

    // 5) dec0 xg (constant over t): hT @ dec0_Wih^T + b   [512, 512]
    sgemm_bias_kernel<<<dim3(4 * DIN / 64, BB / 128), 256>>>(
        hT, d0_Wih, d0_bih, d0_bhh, xgd0, BB, 4 * DIN, DHID);

    // 6) dec0 recurrence (t-stride 0) -> d0 (seq)
    lstm_rec_mma<DIN, 4><<<128, 512, SMEM_DEC>>>(
        d0_Whh, xgd0, (size_t)4 * DIN, 0, seq, nullptr);

    // 7) xgd1 = d0 @ dec1_Wih^T + b   [65536, 512]
    sgemm_bias_kernel<<<dim3(4 * DIN / 64, MT / 128), 256>>>(
        seq, d1_Wih, d1_bih, d1_bhh, xg, MT, 4 * DIN, DIN);

    // 8) dec1 recurrence -> d1 (seq)
    lstm_rec_mma<DIN, 4><<<128, 512, SMEM_DEC>>>(
        d1_Whh, xg, (size_t)TT * 4 * DIN, 4 * DIN, seq, nullptr);

    // 9) out = d1 @ out_W^T + out_b   [65536, 128]
    sgemm_bias_kernel<<<dim3(DIN / 64, MT / 128), 256>>>(
        seq, out_W, out_b, nullptr, out, MT, DIN, DIN);
}

// round 6
// speedup vs baseline: 1.5976x; 1.1733x over previous
#include <cuda_runtime.h>
#include <cuda_bf16.h>
#include <cstdint>
#include <cstddef>

#define BB   512
#define TT   128
#define DIN  128
#define DHID 256

// ---------------------------------------------------------------------------
// Scratch (device globals; no allocations allowed)
// ---------------------------------------------------------------------------
__device__ float g_xg [(size_t)BB * TT * 4 * DHID];
__device__ float g_seq[(size_t)BB * TT * DHID];
__device__ float g_hT [(size_t)BB * DHID];
__device__ float g_xgd0[(size_t)BB * 4 * DIN];

// ---------------------------------------------------------------------------
// Helpers
// ---------------------------------------------------------------------------
__device__ __forceinline__ float sigf(float x) { return 1.0f / (1.0f + __expf(-x)); }
__device__ __forceinline__ float tanhe(float x) {
    x = fminf(fmaxf(x, -15.0f), 15.0f);
    float e = __expf(-2.0f * x);
    return __fdividef(1.0f - e, 1.0f + e);
}
__device__ __forceinline__ uint32_t f2tf32(float x) {
    uint32_t u; asm("cvt.rna.tf32.f32 %0, %1;" : "=r"(u) : "f"(x)); return u;
}
__device__ __forceinline__ uint32_t smem_u32(const void* p) {
    uint32_t a;
    asm("{ .reg .u64 t; cvta.to.shared.u64 t, %1; cvt.u32.u64 %0, t; }" : "=r"(a) : "l"(p));
    return a;
}
__device__ __forceinline__ uint32_t cl_rank() {
    uint32_t r; asm("mov.u32 %0, %%cluster_ctarank;" : "=r"(r)); return r;
}
__device__ __forceinline__ uint32_t mapa_u32(uint32_t addr, uint32_t rank) {
    uint32_t r;
    asm("mapa.shared::cluster.u32 %0, %1, %2;" : "=r"(r) : "r"(addr), "r"(rank));
    return r;
}
__device__ __forceinline__ void st_cluster_v4(uint32_t addr, float a, float b, float c, float d) {
    asm volatile("st.shared::cluster.v4.f32 [%0], {%1,%2,%3,%4};"
                 :: "r"(addr), "f"(a), "f"(b), "f"(c), "f"(d) : "memory");
}
#define CLUSTER_SYNC_() do { \
    asm volatile("barrier.cluster.arrive.aligned;" ::: "memory"); \
    asm volatile("barrier.cluster.wait.aligned;"   ::: "memory"); \
} while (0)

__device__ __forceinline__ void mma_tf32(float4& c, const uint32_t a[4],
                                         uint32_t b0, uint32_t b1) {
    asm volatile(
        "mma.sync.aligned.m16n8k8.row.col.f32.tf32.tf32.f32 "
        "{%0,%1,%2,%3}, {%4,%5,%6,%7}, {%8,%9}, {%0,%1,%2,%3};"
        : "+f"(c.x), "+f"(c.y), "+f"(c.z), "+f"(c.w)
        : "r"(a[0]), "r"(a[1]), "r"(a[2]), "r"(a[3]), "r"(b0), "r"(b1));
}

// ---------------------------------------------------------------------------
// Recurrent LSTM, tensor cores + packed hi/lo fragment layout.
// Cluster of 8 CTAs per batch-tile of 32; rank r owns gate rows
// {g*H + r*JC + cl}. Whh in registers (tf32, warp = (m-group, k-slice),
// MPW m-tiles per warp). hilo[2][Bt][HLS4] float4 holds, per (b, kb, tk),
// {hi(k), hi(k+4), lo(k), lo(k+4)} with k = kb*8+tk — exactly one LDS.128
// per B fragment pair (hi MMA + lo MMA). Phase 2 computes gates (cell state
// in registers, xg prefetched), converts h -> hi/lo, and writes the packed
// float4 straight into all 8 peers' next-step buffer via DSMEM.
// Per step: phase1 -> __syncthreads -> phase2 -> cluster.sync.
// ---------------------------------------------------------------------------
template <int H, int KH, int MPW>
__global__ void __cluster_dims__(8, 1, 1) __launch_bounds__(512, 1)
lstm_rec_mma(const float* __restrict__ Whh,        // [4H][H]
             const float* __restrict__ xg,
             size_t xg_bs, int xg_ts,
             float* __restrict__ out_seq,           // [B][T][H] or null
             float* __restrict__ out_final)         // [B][H]    or null
{
    constexpr int K    = H;
    constexpr int JC   = H / 8;
    constexpr int GR   = 4 * JC;
    constexpr int KB   = K / 8;
    constexpr int KT   = KB / KH;
    constexpr int MG   = (GR / 16) / MPW;
    static_assert(MG * KH == 16, "16 warps");
    constexpr int HLS4 = KB * 4 + 4;        // float4 stride per b (≡4 mod 8)
    constexpr int SG   = 34;
    constexpr int Bt   = 32;
    constexpr int HLF  = 8 * Bt * HLS4;     // floats in hilo[2][Bt][HLS4]

    extern __shared__ float smem[];
    float4* hilo = reinterpret_cast<float4*>(smem);
    float*  gsm  = smem + HLF;              // [KH][GR][SG]

    const int tid = threadIdx.x, wid = tid >> 5, lane = tid & 31;
    const int gid = lane >> 2, tkl = lane & 3;
    const uint32_t r = cl_rank();
    const int b0 = (blockIdx.x >> 3) * Bt;

    const int mg = wid / KH, kh = wid % KH;
    const int kbase = kh * KT * 8;

    // ---- preload A fragments (tf32 in registers) -------------------------
    uint32_t A[MPW][KT][4];
    #pragma unroll
    for (int mp = 0; mp < MPW; ++mp) {
        int m0 = (mg * MPW + mp) * 16;
        int j1 = m0 + gid, j2 = j1 + 8;
        const float* w1 = Whh + (size_t)((j1 / JC) * H + r * JC + (j1 % JC)) * K;
        const float* w2 = Whh + (size_t)((j2 / JC) * H + r * JC + (j2 % JC)) * K;
        #pragma unroll
        for (int kt = 0; kt < KT; ++kt) {
            int k0 = kbase + kt * 8 + tkl;
            A[mp][kt][0] = f2tf32(w1[k0]);
            A[mp][kt][1] = f2tf32(w2[k0]);
            A[mp][kt][2] = f2tf32(w1[k0 + 4]);
            A[mp][kt][3] = f2tf32(w2[k0 + 4]);
        }
    }
    // zero hilo (both buffers)
    for (int i = tid; i < HLF; i += 512) smem[i] = 0.0f;
    __syncthreads();
    CLUSTER_SYNC_();

    // ---- phase-2 work-item identity ---------------------------------------
    constexpr int IT = Bt * (JC / 2);
    const int  pb  = tid / (JC / 2);
    const int  kl  = tid % (JC / 2);
    const int  cl1 = (kl >> 2) * 8 + (kl & 3);   // local col in [0,JC)
    const int  k1  = r * JC + cl1;               // global k (pair: k1, k1+4)
    const int  kbg = k1 >> 3;
    const int  tk2 = k1 & 3;
    const bool act = tid < IT;
    const uint32_t sbase = smem_u32(smem);
    float cv0 = 0.0f, cv1 = 0.0f;

    for (int t = 0; t < TT; ++t) {
        // -------- prefetch xg (hidden behind phase 1) ---------------------
        float xr[8];
        if (act) {
            const float* xgt = xg + (size_t)t * xg_ts + (size_t)(b0 + pb) * xg_bs;
            #pragma unroll
            for (int g = 0; g < 4; ++g) {
                xr[2 * g]     = __ldg(xgt + g * H + k1);
                xr[2 * g + 1] = __ldg(xgt + g * H + k1 + 4);
            }
        }

        // -------- phase 1: tensor-core dots -------------------------------
        {
            const float4* hb = hilo + (size_t)(t & 1) * Bt * HLS4;
            float4 C[MPW][4];
            #pragma unroll
            for (int mp = 0; mp < MPW; ++mp)
                #pragma unroll
                for (int nt = 0; nt < 4; ++nt) C[mp][nt] = make_float4(0.f, 0.f, 0.f, 0.f);

            #pragma unroll
            for (int kt = 0; kt < KT; ++kt) {
                int kb = kh * KT + kt;
                #pragma unroll
                for (int nt = 0; nt < 4; ++nt) {
                    float4 bf = hb[(nt * 8 + gid) * HLS4 + kb * 4 + tkl];
                    uint32_t bh0 = __float_as_uint(bf.x), bh1 = __float_as_uint(bf.y);
                    uint32_t bl0 = __float_as_uint(bf.z), bl1 = __float_as_uint(bf.w);
                    #pragma unroll
                    for (int mp = 0; mp < MPW; ++mp) {
                        mma_tf32(C[mp][nt], A[mp][kt], bh0, bh1);
                        mma_tf32(C[mp][nt], A[mp][kt], bl0, bl1);
                    }
                }
            }
            float* gout = gsm + kh * (GR * SG);
            #pragma unroll
            for (int mp = 0; mp < MPW; ++mp) {
                int m0 = (mg * MPW + mp) * 16;
                #pragma unroll
                for (int nt = 0; nt < 4; ++nt) {
                    int col = nt * 8 + 2 * tkl;
                    *reinterpret_cast<float2*>(&gout[(m0 + gid) * SG + col]) =
                        make_float2(C[mp][nt].x, C[mp][nt].y);
                    *reinterpret_cast<float2*>(&gout[(m0 + gid + 8) * SG + col]) =
                        make_float2(C[mp][nt].z, C[mp][nt].w);
                }
            }
        }
        __syncthreads();

        // -------- phase 2: gates + state + packed broadcast ---------------
        if (act) {
            float s[8];
            #pragma unroll
            for (int g = 0; g < 4; ++g) {
                float a0 = xr[2 * g], a1 = xr[2 * g + 1];
                int row0 = (g * JC + cl1) * SG + pb;
                #pragma unroll
                for (int khx = 0; khx < KH; ++khx) {
                    const float* gp = gsm + khx * (GR * SG);
                    a0 += gp[row0];
                    a1 += gp[row0 + 4 * SG];
                }
                s[2 * g] = a0; s[2 * g + 1] = a1;
            }
            float i0 = sigf(s[0]), i1 = sigf(s[1]);
            float f0 = sigf(s[2]), f1 = sigf(s[3]);
            float g0 = tanhe(s[4]), g1 = tanhe(s[5]);
            float o0 = sigf(s[6]), o1 = sigf(s[7]);
            cv0 = f0 * cv0 + i0 * g0;
            cv1 = f1 * cv1 + i1 * g1;
            float h1 = o0 * tanhe(cv0);
            float h2 = o1 * tanhe(cv1);

            if (out_seq) {
                float* ob = out_seq + ((size_t)(b0 + pb) * TT + t) * H;
                ob[k1] = h1; ob[k1 + 4] = h2;
            }
            if (out_final && t == TT - 1) {
                float* of = out_final + (size_t)(b0 + pb) * H;
                of[k1] = h1; of[k1 + 4] = h2;
            }

            uint32_t hi1 = f2tf32(h1), hi2 = f2tf32(h2);
            float lo1f = h1 - __uint_as_float(hi1);
            float lo2f = h2 - __uint_as_float(hi2);
            uint32_t lo1 = f2tf32(lo1f), lo2 = f2tf32(lo2f);

            uint32_t fo = sbase +
                (uint32_t)(((((t + 1) & 1) * Bt + pb) * HLS4 + kbg * 4 + tk2) * 16);
            #pragma unroll
            for (int p = 0; p < 8; ++p) {
                uint32_t ra = mapa_u32(fo, (uint32_t)p);
                st_cluster_v4(ra, __uint_as_float(hi1), __uint_as_float(hi2),
                                  __uint_as_float(lo1), __uint_as_float(lo2));
            }
        }
        CLUSTER_SYNC_();
    }
}

// ---------------------------------------------------------------------------
// SGEMM with fused bias (unchanged, proven): C = A*B^T + b1 (+ b2)
// ---------------------------------------------------------------------------
__global__ __launch_bounds__(256) void sgemm_bias_kernel(
    const float* __restrict__ A, const float* __restrict__ B,
    const float* __restrict__ b1, const float* __restrict__ b2,
    float* __restrict__ C, int M, int N, int K)
{
    __shared__ float As[16][132];
    __shared__ float Bs[16][68];

    const int tid = threadIdx.x;
    const int bm = blockIdx.y * 128;
    const int bn = blockIdx.x * 64;
    const int tx = tid & 15;
    const int ty = tid >> 4;
    const int lrow = tid >> 2;
    const int lcol = (tid & 3) << 2;

    float acc[8][4];
    #pragma unroll
    for (int i = 0; i < 8; ++i)
        #pragma unroll
        for (int j = 0; j < 4; ++j) acc[i][j] = 0.0f;

    const float* Ap0 = A + (size_t)(bm + lrow) * K + lcol;
    const float* Ap1 = A + (size_t)(bm + lrow + 64) * K + lcol;
    const float* Bp  = B + (size_t)(bn + lrow) * K + lcol;

    for (int k0 = 0; k0 < K; k0 += 16) {
        float4 a0 = *reinterpret_cast<const float4*>(Ap0 + k0);
        float4 a1 = *reinterpret_cast<const float4*>(Ap1 + k0);
        float4 bv = *reinterpret_cast<const float4*>(Bp + k0);
        As[lcol + 0][lrow]      = a0.x; As[lcol + 1][lrow]      = a0.y;
        As[lcol + 2][lrow]      = a0.z; As[lcol + 3][lrow]      = a0.w;
        As[lcol + 0][lrow + 64] = a1.x; As[lcol + 1][lrow + 64] = a1.y;
        As[lcol + 2][lrow + 64] = a1.z; As[lcol + 3][lrow + 64] = a1.w;
        Bs[lcol + 0][lrow] = bv.x; Bs[lcol + 1][lrow] = bv.y;
        Bs[lcol + 2][lrow] = bv.z; Bs[lcol + 3][lrow] = bv.w;
        __syncthreads();

        #pragma unroll
        for (int k = 0; k < 16; ++k) {
            float av[8], bw[4];
            *reinterpret_cast<float4*>(av)     = *reinterpret_cast<const float4*>(&As[k][ty * 8]);
            *reinterpret_cast<float4*>(av + 4) = *reinterpret_cast<const float4*>(&As[k][ty * 8 + 4]);
            *reinterpret_cast<float4*>(bw)     = *reinterpret_cast<const float4*>(&Bs[k][tx * 4]);
            #pragma unroll
            for (int i = 0; i < 8; ++i)
                #pragma unroll
                for (int j = 0; j < 4; ++j)
                    acc[i][j] += av[i] * bw[j];
        }
        __syncthreads();
    }

    float bias[4];
    #pragma unroll
    for (int j = 0; j < 4; ++j) {
        int n = bn + tx * 4 + j;
        bias[j] = b1[n] + (b2 ? b2[n] : 0.0f);
    }
    #pragma unroll
    for (int i = 0; i < 8; ++i) {
        float4 o = make_float4(acc[i][0] + bias[0], acc[i][1] + bias[1],
                               acc[i][2] + bias[2], acc[i][3] + bias[3]);
        *reinterpret_cast<float4*>(C + (size_t)(bm + ty * 8 + i) * N + bn + tx * 4) = o;
    }
}

// ---------------------------------------------------------------------------
// Launch
// ---------------------------------------------------------------------------
// enc: hilo = 8*32*132 floats = 135168 B ; gsm = 4*128*34*4 = 69632 B
static const int SMEM_ENC = 135168 + 69632;   // 204800
// dec: hilo = 8*32*68 floats = 69632 B ; gsm = 4*64*34*4 = 34816 B
static const int SMEM_DEC = 69632 + 34816;    // 104448

extern "C" void kernel_launch(void* const* d_in, const int* in_sizes, int n_in,
                              void* d_out, int out_size)
{
    (void)in_sizes; (void)n_in; (void)out_size;
    const float* x        = (const float*)d_in[0];
    const float* e0_Wih   = (const float*)d_in[1];
    const float* e0_Whh   = (const float*)d_in[2];
    const float* e0_bih   = (const float*)d_in[3];
    const float* e0_bhh   = (const float*)d_in[4];
    const float* e1_Wih   = (const float*)d_in[5];
    const float* e1_Whh   = (const float*)d_in[6];
    const float* e1_bih   = (const float*)d_in[7];
    const float* e1_bhh   = (const float*)d_in[8];
    const float* d0_Wih   = (const float*)d_in[9];
    const float* d0_Whh   = (const float*)d_in[10];
    const float* d0_bih   = (const float*)d_in[11];
    const float* d0_bhh   = (const float*)d_in[12];
    const float* d1_Wih   = (const float*)d_in[13];
    const float* d1_Whh   = (const float*)d_in[14];
    const float* d1_bih   = (const float*)d_in[15];
    const float* d1_bhh   = (const float*)d_in[16];
    const float* out_W    = (const float*)d_in[17];
    const float* out_b    = (const float*)d_in[18];
    float* out = (float*)d_out;

    float *xg, *seq, *hT, *xgd0;
    cudaGetSymbolAddress((void**)&xg,   g_xg);
    cudaGetSymbolAddress((void**)&seq,  g_seq);
    cudaGetSymbolAddress((void**)&hT,   g_hT);
    cudaGetSymbolAddress((void**)&xgd0, g_xgd0);

    cudaFuncSetAttribute(lstm_rec_mma<DHID, 4, 2>,
                         cudaFuncAttributeMaxDynamicSharedMemorySize, SMEM_ENC);
    cudaFuncSetAttribute(lstm_rec_mma<DIN, 4, 1>,
                         cudaFuncAttributeMaxDynamicSharedMemorySize, SMEM_DEC);

    const int MT = BB * TT;  // 65536

    // 1) xg0 = x @ enc0_Wih^T + b
    sgemm_bias_kernel<<<dim3(4 * DHID / 64, MT / 128), 256>>>(
        x, e0_Wih, e0_bih, e0_bhh, xg, MT, 4 * DHID, DIN);

    // 2) enc0 recurrence -> e0 (seq)
    lstm_rec_mma<DHID, 4, 2><<<128, 512, SMEM_ENC>>>(
        e0_Whh, xg, (size_t)TT * 4 * DHID, 4 * DHID, seq, nullptr);

    // 3) xg1 = e0 @ enc1_Wih^T + b
    sgemm_bias_kernel<<<dim3(4 * DHID / 64, MT / 128), 256>>>(
        seq, e1_Wih, e1_bih, e1_bhh, xg, MT, 4 * DHID, DHID);

    // 4) enc1 recurrence -> hT only
    lstm_rec_mma<DHID, 4, 2><<<128, 512, SMEM_ENC>>>(
        e1_Whh, xg, (size_t)TT * 4 * DHID, 4 * DHID, nullptr, hT);

    // 5) dec0 xg (constant over t)
    sgemm_bias_kernel<<<dim3(4 * DIN / 64, BB / 128), 256>>>(
        hT, d0_Wih, d0_bih, d0_bhh, xgd0, BB, 4 * DIN, DHID);

    // 6) dec0 recurrence (t-stride 0) -> d0 (seq)
    lstm_rec_mma<DIN, 4, 1><<<128, 512, SMEM_DEC>>>(
        d0_Whh, xgd0, (size_t)4 * DIN, 0, seq, nullptr);

    // 7) xgd1 = d0 @ dec1_Wih^T + b
    sgemm_bias_kernel<<<dim3(4 * DIN / 64, MT / 128), 256>>>(
        seq, d1_Wih, d1_bih, d1_bhh, xg, MT, 4 * DIN, DIN);

    // 8) dec1 recurrence -> d1 (seq)
    lstm_rec_mma<DIN, 4, 1><<<128, 512, SMEM_DEC>>>(
        d1_Whh, xg, (size_t)TT * 4 * DIN, 4 * DIN, seq, nullptr);

    // 9) out = d1 @ out_W^T + out_b
    sgemm_bias_kernel<<<dim3(DIN / 64, MT / 128), 256>>>(
        seq, out_W, out_b, nullptr, out, MT, DIN, DIN);
}

// round 7
// speedup vs baseline: 2.0150x; 1.2613x over previous
#include <cuda_runtime.h>
#include <cuda_bf16.h>
#include <cstdint>
#include <cstddef>

#define BB   512
#define TT   128
#define DIN  128
#define DHID 256

// ---------------------------------------------------------------------------
// Scratch (device globals; no allocations allowed)
// ---------------------------------------------------------------------------
__device__ float g_xg [(size_t)BB * TT * 4 * DHID];
__device__ float g_seq[(size_t)BB * TT * DHID];
__device__ float g_hT [(size_t)BB * DHID];
__device__ float g_xgd0[(size_t)BB * 4 * DIN];

// ---------------------------------------------------------------------------
// Helpers
// ---------------------------------------------------------------------------
__device__ __forceinline__ float sigf(float x) { return 1.0f / (1.0f + __expf(-x)); }
__device__ __forceinline__ float tanhe(float x) {
    x = fminf(fmaxf(x, -15.0f), 15.0f);
    float e = __expf(-2.0f * x);
    return __fdividef(1.0f - e, 1.0f + e);
}
// pack two floats to bf16x2; 'a' (smaller k index) -> LOW half, 'b' -> HIGH half
__device__ __forceinline__ uint32_t pack_bf16x2(float a, float b) {
    uint32_t r; asm("cvt.rn.bf16x2.f32 %0, %1, %2;" : "=r"(r) : "f"(b), "f"(a)); return r;
}
// split f0,f1 into bf16 hi pair + bf16 residual-lo pair
__device__ __forceinline__ void split_pack(float f0, float f1,
                                           uint32_t& hi2, uint32_t& lo2) {
    float h0 = __bfloat162float(__float2bfloat16(f0));
    float h1 = __bfloat162float(__float2bfloat16(f1));
    hi2 = pack_bf16x2(h0, h1);
    lo2 = pack_bf16x2(f0 - h0, f1 - h1);
}
__device__ __forceinline__ uint32_t smem_u32(const void* p) {
    uint32_t a;
    asm("{ .reg .u64 t; cvta.to.shared.u64 t, %1; cvt.u32.u64 %0, t; }" : "=r"(a) : "l"(p));
    return a;
}
__device__ __forceinline__ uint32_t cl_rank() {
    uint32_t r; asm("mov.u32 %0, %%cluster_ctarank;" : "=r"(r)); return r;
}
__device__ __forceinline__ uint32_t mapa_u32(uint32_t addr, uint32_t rank) {
    uint32_t r;
    asm("mapa.shared::cluster.u32 %0, %1, %2;" : "=r"(r) : "r"(addr), "r"(rank));
    return r;
}
__device__ __forceinline__ void st_cluster_v2(uint32_t addr, uint32_t a, uint32_t b) {
    asm volatile("st.shared::cluster.v2.b32 [%0], {%1,%2};"
                 :: "r"(addr), "r"(a), "r"(b) : "memory");
}
#define CLUSTER_SYNC_() do { \
    asm volatile("barrier.cluster.arrive.aligned;" ::: "memory"); \
    asm volatile("barrier.cluster.wait.aligned;"   ::: "memory"); \
} while (0)

__device__ __forceinline__ void mma_bf16(float4& c, const uint32_t a[4],
                                         uint32_t b0, uint32_t b1) {
    asm volatile(
        "mma.sync.aligned.m16n8k16.row.col.f32.bf16.bf16.f32 "
        "{%0,%1,%2,%3}, {%4,%5,%6,%7}, {%8,%9}, {%0,%1,%2,%3};"
        : "+f"(c.x), "+f"(c.y), "+f"(c.z), "+f"(c.w)
        : "r"(a[0]), "r"(a[1]), "r"(a[2]), "r"(a[3]), "r"(b0), "r"(b1));
}

// ---------------------------------------------------------------------------
// Recurrent LSTM, bf16 hi/lo tensor cores.
// Cluster of 8 CTAs per batch-tile of 32; rank r owns gate rows
// {g*H + r*JC + cl}. Whh in registers as bf16 hi + residual-lo fragments
// (warp = (m-group, k-slice), MPW m-tiles). h exchanged as packed uint2
// {hi bf16x2, lo bf16x2} per (b, k-pair): one LDS.64 per B half-fragment.
// 3 MMAs per k16-tile: Whi*hhi + Whi*hlo + Wlo*hhi (Wlo*hlo ~2^-16, dropped).
// Phase 2: gates (cell state in registers, xg prefetched), split h -> hi/lo,
// DSMEM-broadcast one uint2 to all 8 peers. One __syncthreads + one
// cluster.sync per step.
// ---------------------------------------------------------------------------
template <int H, int KH, int MPW>
__global__ void __cluster_dims__(8, 1, 1) __launch_bounds__(512, 1)
lstm_rec_bf16(const float* __restrict__ Whh,        // [4H][H]
              const float* __restrict__ xg,
              size_t xg_bs, int xg_ts,
              float* __restrict__ out_seq,           // [B][T][H] or null
              float* __restrict__ out_final)         // [B][H]    or null
{
    constexpr int K    = H;
    constexpr int JC   = H / 8;
    constexpr int GR   = 4 * JC;
    constexpr int KT   = (K / 16) / KH;     // k16-tiles per warp (enc 4, dec 2)
    constexpr int MG   = (GR / 16) / MPW;
    static_assert(MG * KH == 16, "16 warps");
    constexpr int HLS2 = K / 2 + 4;         // uint2 stride per b; ≡4 mod 16
    static_assert(HLS2 % 16 == 4, "bank layout");
    constexpr int SG   = 34;
    constexpr int Bt   = 32;
    constexpr int HLU  = 2 * Bt * HLS2;     // uint2 count (both buffers)

    extern __shared__ char smem_raw[];
    uint2* hl  = reinterpret_cast<uint2*>(smem_raw);
    float* gsm = reinterpret_cast<float*>(smem_raw + (size_t)HLU * 8);

    const int tid = threadIdx.x, wid = tid >> 5, lane = tid & 31;
    const int gid = lane >> 2, tk = lane & 3;
    const uint32_t r = cl_rank();
    const int b0 = (blockIdx.x >> 3) * Bt;

    const int mg = wid / KH, kh = wid % KH;

    // ---- preload A fragments (bf16 hi/lo in registers) --------------------
    uint32_t Ahi[MPW][KT][4], Alo[MPW][KT][4];
    #pragma unroll
    for (int mp = 0; mp < MPW; ++mp) {
        int m0 = (mg * MPW + mp) * 16;
        int j1 = m0 + gid, j2 = j1 + 8;
        const float* w1 = Whh + (size_t)((j1 / JC) * H + r * JC + (j1 % JC)) * K;
        const float* w2 = Whh + (size_t)((j2 / JC) * H + r * JC + (j2 % JC)) * K;
        #pragma unroll
        for (int kt = 0; kt < KT; ++kt) {
            int ka = (kh * KT + kt) * 16 + 2 * tk;
            split_pack(w1[ka],     w1[ka + 1], Ahi[mp][kt][0], Alo[mp][kt][0]);
            split_pack(w2[ka],     w2[ka + 1], Ahi[mp][kt][1], Alo[mp][kt][1]);
            split_pack(w1[ka + 8], w1[ka + 9], Ahi[mp][kt][2], Alo[mp][kt][2]);
            split_pack(w2[ka + 8], w2[ka + 9], Ahi[mp][kt][3], Alo[mp][kt][3]);
        }
    }
    // zero h exchange buffers (bf16 zeros are bit-zero)
    for (int i = tid; i < 2 * HLU; i += 512)
        reinterpret_cast<uint32_t*>(hl)[i] = 0u;
    __syncthreads();
    CLUSTER_SYNC_();

    // ---- phase-2 identity --------------------------------------------------
    constexpr int IT = Bt * (JC / 2);
    const int  pb  = tid / (JC / 2);
    const int  kl  = tid % (JC / 2);
    const int  k0  = r * JC + 2 * kl;       // adjacent global k pair (k0, k0+1)
    const int  kpg = k0 >> 1;               // global pair index
    const bool act = tid < IT;
    const uint32_t sbase = smem_u32(smem_raw);
    float cv0 = 0.0f, cv1 = 0.0f;

    for (int t = 0; t < TT; ++t) {
        // -------- prefetch xg (hidden behind phase 1) ----------------------
        float2 xr[4];
        if (act) {
            const float* xgt = xg + (size_t)t * xg_ts + (size_t)(b0 + pb) * xg_bs;
            #pragma unroll
            for (int g = 0; g < 4; ++g)
                xr[g] = *reinterpret_cast<const float2*>(xgt + g * H + k0);
        }

        // -------- phase 1: bf16 tensor-core dots ---------------------------
        {
            const uint2* hb = hl + (size_t)(t & 1) * Bt * HLS2;
            float4 C[MPW][4];
            #pragma unroll
            for (int mp = 0; mp < MPW; ++mp)
                #pragma unroll
                for (int nt = 0; nt < 4; ++nt) C[mp][nt] = make_float4(0.f, 0.f, 0.f, 0.f);

            #pragma unroll
            for (int kt = 0; kt < KT; ++kt) {
                int kp0 = (kh * KT + kt) * 8 + tk;
                #pragma unroll
                for (int nt = 0; nt < 4; ++nt) {
                    int n = nt * 8 + gid;
                    uint2 u0 = hb[n * HLS2 + kp0];        // {b0hi, b0lo}
                    uint2 u1 = hb[n * HLS2 + kp0 + 4];    // {b1hi, b1lo}
                    #pragma unroll
                    for (int mp = 0; mp < MPW; ++mp) {
                        mma_bf16(C[mp][nt], Ahi[mp][kt], u0.x, u1.x);
                        mma_bf16(C[mp][nt], Ahi[mp][kt], u0.y, u1.y);
                        mma_bf16(C[mp][nt], Alo[mp][kt], u0.x, u1.x);
                    }
                }
            }
            float* gout = gsm + kh * (GR * SG);
            #pragma unroll
            for (int mp = 0; mp < MPW; ++mp) {
                int m0 = (mg * MPW + mp) * 16;
                #pragma unroll
                for (int nt = 0; nt < 4; ++nt) {
                    int col = nt * 8 + 2 * tk;
                    *reinterpret_cast<float2*>(&gout[(m0 + gid) * SG + col]) =
                        make_float2(C[mp][nt].x, C[mp][nt].y);
                    *reinterpret_cast<float2*>(&gout[(m0 + gid + 8) * SG + col]) =
                        make_float2(C[mp][nt].z, C[mp][nt].w);
                }
            }
        }
        __syncthreads();

        // -------- phase 2: gates + state + packed broadcast ----------------
        if (act) {
            float s0[4], s1[4];
            #pragma unroll
            for (int g = 0; g < 4; ++g) {
                float a0 = xr[g].x, a1 = xr[g].y;
                int row = (g * JC + 2 * kl) * SG + pb;
                #pragma unroll
                for (int khx = 0; khx < KH; ++khx) {
                    const float* gp = gsm + khx * (GR * SG);
                    a0 += gp[row];
                    a1 += gp[row + SG];
                }
                s0[g] = a0; s1[g] = a1;
            }
            float i0 = sigf(s0[0]), i1 = sigf(s1[0]);
            float f0 = sigf(s0[1]), f1 = sigf(s1[1]);
            float g0 = tanhe(s0[2]), g1 = tanhe(s1[2]);
            float o0 = sigf(s0[3]), o1 = sigf(s1[3]);
            cv0 = f0 * cv0 + i0 * g0;
            cv1 = f1 * cv1 + i1 * g1;
            float h0v = o0 * tanhe(cv0);
            float h1v = o1 * tanhe(cv1);

            if (out_seq)
                *reinterpret_cast<float2*>(
                    &out_seq[((size_t)(b0 + pb) * TT + t) * H + k0]) =
                    make_float2(h0v, h1v);
            if (out_final && t == TT - 1)
                *reinterpret_cast<float2*>(
                    &out_final[(size_t)(b0 + pb) * H + k0]) =
                    make_float2(h0v, h1v);

            uint32_t hi2, lo2;
            split_pack(h0v, h1v, hi2, lo2);

            uint32_t fo = sbase +
                (uint32_t)(((((t + 1) & 1) * Bt + pb) * HLS2 + kpg) * 8);
            #pragma unroll
            for (int p = 0; p < 8; ++p) {
                uint32_t ra = mapa_u32(fo, (uint32_t)p);
                st_cluster_v2(ra, hi2, lo2);
            }
        }
        CLUSTER_SYNC_();
    }
}

// ---------------------------------------------------------------------------
// Tensor-core GEMM with fused bias, bf16 hi/lo (fp32-accurate):
//   C[m][n] = sum_k A[m][k]*B[n][k] + b1[n] (+ b2[n])
// BM=128 BN=64 BK=32; 256 threads = 8 warps (4m x 2n), warp tile 32x32.
// A and B converted inline fp32 -> {bf16 hi, bf16 lo} packed uint2 per k-pair.
// 3 MMAs per k16: Ahi*Bhi + Ahi*Blo + Alo*Bhi.
// ---------------------------------------------------------------------------
__global__ __launch_bounds__(256) void hgemm_bias_kernel(
    const float* __restrict__ A, const float* __restrict__ B,
    const float* __restrict__ b1, const float* __restrict__ b2,
    float* __restrict__ C, int M, int N, int K)
{
    __shared__ uint2 As[128][20];   // [m][kp]  (kp < 16 used; stride 20 ≡4 mod 16)
    __shared__ uint2 Bs[64][20];    // [n][kp]

    const int tid = threadIdx.x, wid = tid >> 5, lane = tid & 31;
    const int gid = lane >> 2, tk = lane & 3;
    const int bm = blockIdx.y * 128;
    const int bn = blockIdx.x * 64;
    const int wm = (wid & 3) * 32;       // warp m offset
    const int wn = (wid >> 2) * 32;      // warp n offset

    float4 Cc[2][4];
    #pragma unroll
    for (int mp = 0; mp < 2; ++mp)
        #pragma unroll
        for (int nt = 0; nt < 4; ++nt) Cc[mp][nt] = make_float4(0.f, 0.f, 0.f, 0.f);

    const int arow = tid >> 1, acb = (tid & 1) * 16;   // A: 128 rows x 32 cols
    const int brow = tid >> 2, bcb = (tid & 3) * 8;    // B:  64 rows x 32 cols
    const float* Ap = A + (size_t)(bm + arow) * K + acb;
    const float* Bp = B + (size_t)(bn + brow) * K + bcb;

    for (int k0 = 0; k0 < K; k0 += 32) {
        // ---- load + convert A tile ----
        #pragma unroll
        for (int v = 0; v < 4; ++v) {
            float4 fv = *reinterpret_cast<const float4*>(Ap + k0 + v * 4);
            uint32_t h0, l0, h1, l1;
            split_pack(fv.x, fv.y, h0, l0);
            split_pack(fv.z, fv.w, h1, l1);
            As[arow][acb / 2 + v * 2]     = make_uint2(h0, l0);
            As[arow][acb / 2 + v * 2 + 1] = make_uint2(h1, l1);
        }
        // ---- load + convert B tile ----
        #pragma unroll
        for (int v = 0; v < 2; ++v) {
            float4 fv = *reinterpret_cast<const float4*>(Bp + k0 + v * 4);
            uint32_t h0, l0, h1, l1;
            split_pack(fv.x, fv.y, h0, l0);
            split_pack(fv.z, fv.w, h1, l1);
            Bs[brow][bcb / 2 + v * 2]     = make_uint2(h0, l0);
            Bs[brow][bcb / 2 + v * 2 + 1] = make_uint2(h1, l1);
        }
        __syncthreads();

        #pragma unroll
        for (int kt = 0; kt < 2; ++kt) {
            int kp = kt * 8 + tk;
            uint32_t Ah[2][4], Al[2][4];
            #pragma unroll
            for (int mp = 0; mp < 2; ++mp) {
                int r1 = wm + mp * 16 + gid;
                uint2 u00 = As[r1][kp],     u01 = As[r1][kp + 4];
                uint2 u10 = As[r1 + 8][kp], u11 = As[r1 + 8][kp + 4];
                Ah[mp][0] = u00.x; Ah[mp][1] = u10.x; Ah[mp][2] = u01.x; Ah[mp][3] = u11.x;
                Al[mp][0] = u00.y; Al[mp][1] = u10.y; Al[mp][2] = u01.y; Al[mp][3] = u11.y;
            }
            #pragma unroll
            for (int nt = 0; nt < 4; ++nt) {
                int n = wn + nt * 8 + gid;
                uint2 u0 = Bs[n][kp];
                uint2 u1 = Bs[n][kp + 4];
                #pragma unroll
                for (int mp = 0; mp < 2; ++mp) {
                    mma_bf16(Cc[mp][nt], Ah[mp], u0.x, u1.x);
                    mma_bf16(Cc[mp][nt], Ah[mp], u0.y, u1.y);
                    mma_bf16(Cc[mp][nt], Al[mp], u0.x, u1.x);
                }
            }
        }
        __syncthreads();
    }

    // ---- epilogue: bias + store ----
    #pragma unroll
    for (int nt = 0; nt < 4; ++nt) {
        int n = bn + wn + nt * 8 + 2 * tk;
        float bb0 = b1[n]     + (b2 ? b2[n]     : 0.0f);
        float bb1 = b1[n + 1] + (b2 ? b2[n + 1] : 0.0f);
        #pragma unroll
        for (int mp = 0; mp < 2; ++mp) {
            int m1 = bm + wm + mp * 16 + gid;
            *reinterpret_cast<float2*>(C + (size_t)m1 * N + n) =
                make_float2(Cc[mp][nt].x + bb0, Cc[mp][nt].y + bb1);
            *reinterpret_cast<float2*>(C + (size_t)(m1 + 8) * N + n) =
                make_float2(Cc[mp][nt].z + bb0, Cc[mp][nt].w + bb1);
        }
    }
}

// ---------------------------------------------------------------------------
// Launch
// ---------------------------------------------------------------------------
// enc: hl = 2*32*132 uint2 = 67584 B ; gsm = 4*128*34*4 = 69632 B
static const int SMEM_ENC = 67584 + 69632;   // 137216
// dec: hl = 2*32*68 uint2 = 34816 B ; gsm = 4*64*34*4 = 34816 B
static const int SMEM_DEC = 34816 + 34816;   // 69632

extern "C" void kernel_launch(void* const* d_in, const int* in_sizes, int n_in,
                              void* d_out, int out_size)
{
    (void)in_sizes; (void)n_in; (void)out_size;
    const float* x        = (const float*)d_in[0];
    const float* e0_Wih   = (const float*)d_in[1];
    const float* e0_Whh   = (const float*)d_in[2];
    const float* e0_bih   = (const float*)d_in[3];
    const float* e0_bhh   = (const float*)d_in[4];
    const float* e1_Wih   = (const float*)d_in[5];
    const float* e1_Whh   = (const float*)d_in[6];
    const float* e1_bih   = (const float*)d_in[7];
    const float* e1_bhh   = (const float*)d_in[8];
    const float* d0_Wih   = (const float*)d_in[9];
    const float* d0_Whh   = (const float*)d_in[10];
    const float* d0_bih   = (const float*)d_in[11];
    const float* d0_bhh   = (const float*)d_in[12];
    const float* d1_Wih   = (const float*)d_in[13];
    const float* d1_Whh   = (const float*)d_in[14];
    const float* d1_bih   = (const float*)d_in[15];
    const float* d1_bhh   = (const float*)d_in[16];
    const float* out_W    = (const float*)d_in[17];
    const float* out_b    = (const float*)d_in[18];
    float* out = (float*)d_out;

    float *xg, *seq, *hT, *xgd0;
    cudaGetSymbolAddress((void**)&xg,   g_xg);
    cudaGetSymbolAddress((void**)&seq,  g_seq);
    cudaGetSymbolAddress((void**)&hT,   g_hT);
    cudaGetSymbolAddress((void**)&xgd0, g_xgd0);

    cudaFuncSetAttribute(lstm_rec_bf16<DHID, 4, 2>,
                         cudaFuncAttributeMaxDynamicSharedMemorySize, SMEM_ENC);
    cudaFuncSetAttribute(lstm_rec_bf16<DIN, 4, 1>,
                         cudaFuncAttributeMaxDynamicSharedMemorySize, SMEM_DEC);

    const int MT = BB * TT;  // 65536

    // 1) xg0 = x @ enc0_Wih^T + b   [65536, 1024] K=128
    hgemm_bias_kernel<<<dim3(4 * DHID / 64, MT / 128), 256>>>(
        x, e0_Wih, e0_bih, e0_bhh, xg, MT, 4 * DHID, DIN);

    // 2) enc0 recurrence -> e0 (seq)
    lstm_rec_bf16<DHID, 4, 2><<<128, 512, SMEM_ENC>>>(
        e0_Whh, xg, (size_t)TT * 4 * DHID, 4 * DHID, seq, nullptr);

    // 3) xg1 = e0 @ enc1_Wih^T + b   [65536, 1024] K=256
    hgemm_bias_kernel<<<dim3(4 * DHID / 64, MT / 128), 256>>>(
        seq, e1_Wih, e1_bih, e1_bhh, xg, MT, 4 * DHID, DHID);

    // 4) enc1 recurrence -> hT only
    lstm_rec_bf16<DHID, 4, 2><<<128, 512, SMEM_ENC>>>(
        e1_Whh, xg, (size_t)TT * 4 * DHID, 4 * DHID, nullptr, hT);

    // 5) dec0 xg (constant over t): [512, 512] K=256
    hgemm_bias_kernel<<<dim3(4 * DIN / 64, BB / 128), 256>>>(
        hT, d0_Wih, d0_bih, d0_bhh, xgd0, BB, 4 * DIN, DHID);

    // 6) dec0 recurrence (t-stride 0) -> d0 (seq)
    lstm_rec_bf16<DIN, 4, 1><<<128, 512, SMEM_DEC>>>(
        d0_Whh, xgd0, (size_t)4 * DIN, 0, seq, nullptr);

    // 7) xgd1 = d0 @ dec1_Wih^T + b   [65536, 512] K=128
    hgemm_bias_kernel<<<dim3(4 * DIN / 64, MT / 128), 256>>>(
        seq, d1_Wih, d1_bih, d1_bhh, xg, MT, 4 * DIN, DIN);

    // 8) dec1 recurrence -> d1 (seq)
    lstm_rec_bf16<DIN, 4, 1><<<128, 512, SMEM_DEC>>>(
        d1_Whh, xg, (size_t)TT * 4 * DIN, 4 * DIN, seq, nullptr);

    // 9) out = d1 @ out_W^T + out_b   [65536, 128] K=128
    hgemm_bias_kernel<<<dim3(DIN / 64, MT / 128), 256>>>(
        seq, out_W, out_b, nullptr, out, MT, DIN, DIN);
}

// round 8
// speedup vs baseline: 2.1207x; 1.0525x over previous
#include <cuda_runtime.h>
#include <cuda_bf16.h>
#include <cstdint>
#include <cstddef>

#define BB   512
#define TT   128
#define DIN  128
#define DHID 256

// ---------------------------------------------------------------------------
// Scratch (device globals; no allocations allowed)
// ---------------------------------------------------------------------------
__device__ float g_xg  [(size_t)BB * TT * 4 * DHID];   // fp32 gate pre-activations
__device__ uint2 g_pk  [(size_t)BB * TT * DHID / 2];   // packed hi/lo activations (x / e0 / d0 / d1)
__device__ uint2 g_wpk [(size_t)4 * DHID * DHID / 2];  // packed weights (reused per GEMM)
__device__ uint2 g_hTpk[(size_t)BB * DHID / 2];        // packed hT
__device__ float g_xgd0[(size_t)BB * 4 * DIN];         // dec0 xg (constant over t)

// ---------------------------------------------------------------------------
// Helpers
// ---------------------------------------------------------------------------
__device__ __forceinline__ float sigf(float x) { return 1.0f / (1.0f + __expf(-x)); }
__device__ __forceinline__ float tanhe(float x) {
    x = fminf(fmaxf(x, -15.0f), 15.0f);
    float e = __expf(-2.0f * x);
    return __fdividef(1.0f - e, 1.0f + e);
}
// pack two floats to bf16x2; 'a' (smaller k index) -> LOW half
__device__ __forceinline__ uint32_t pack_bf16x2(float a, float b) {
    uint32_t r; asm("cvt.rn.bf16x2.f32 %0, %1, %2;" : "=r"(r) : "f"(b), "f"(a)); return r;
}
__device__ __forceinline__ void split_pack(float f0, float f1,
                                           uint32_t& hi2, uint32_t& lo2) {
    float h0 = __bfloat162float(__float2bfloat16(f0));
    float h1 = __bfloat162float(__float2bfloat16(f1));
    hi2 = pack_bf16x2(h0, h1);
    lo2 = pack_bf16x2(f0 - h0, f1 - h1);
}
__device__ __forceinline__ uint32_t smem_u32(const void* p) {
    uint32_t a;
    asm("{ .reg .u64 t; cvta.to.shared.u64 t, %1; cvt.u32.u64 %0, t; }" : "=r"(a) : "l"(p));
    return a;
}
__device__ __forceinline__ uint32_t cl_rank() {
    uint32_t r; asm("mov.u32 %0, %%cluster_ctarank;" : "=r"(r)); return r;
}
__device__ __forceinline__ uint32_t mapa_u32(uint32_t addr, uint32_t rank) {
    uint32_t r;
    asm("mapa.shared::cluster.u32 %0, %1, %2;" : "=r"(r) : "r"(addr), "r"(rank));
    return r;
}
__device__ __forceinline__ void st_cluster_v2(uint32_t addr, uint32_t a, uint32_t b) {
    asm volatile("st.shared::cluster.v2.b32 [%0], {%1,%2};"
                 :: "r"(addr), "r"(a), "r"(b) : "memory");
}
#define CLUSTER_SYNC_() do { \
    asm volatile("barrier.cluster.arrive.aligned;" ::: "memory"); \
    asm volatile("barrier.cluster.wait.aligned;"   ::: "memory"); \
} while (0)

__device__ __forceinline__ void mma_bf16(float4& c, const uint32_t a[4],
                                         uint32_t b0, uint32_t b1) {
    asm volatile(
        "mma.sync.aligned.m16n8k16.row.col.f32.bf16.bf16.f32 "
        "{%0,%1,%2,%3}, {%4,%5,%6,%7}, {%8,%9}, {%0,%1,%2,%3};"
        : "+f"(c.x), "+f"(c.y), "+f"(c.z), "+f"(c.w)
        : "r"(a[0]), "r"(a[1]), "r"(a[2]), "r"(a[3]), "r"(b0), "r"(b1));
}

// ---------------------------------------------------------------------------
// Recurrent LSTM: bf16 hi/lo tensor cores + two-half software pipeline.
// Cluster of 8 CTAs per batch-tile of 32 (halves A = b 0-15, B = b 16-31).
// Timestep = 2 brackets: [P2(A,t); P1(B,t); csync][P2(B,t); P1(A,t+1); csync]
// P2 issues its DSMEM broadcast early so the drain overlaps P1's MMAs.
// Whh in registers (bf16 hi + residual lo). h exchanged as packed uint2
// {hi bf16x2, lo bf16x2} per k-pair. out_seq / out_final written PACKED.
// ---------------------------------------------------------------------------
template <int H, int KH, int MPW>
__global__ void __cluster_dims__(8, 1, 1) __launch_bounds__(512, 1)
lstm_rec_pipe(const float* __restrict__ Whh,        // [4H][H]
              const float* __restrict__ xg,
              size_t xg_bs, int xg_ts,
              uint2* __restrict__ out_seq,           // [B][T][H/2] packed or null
              uint2* __restrict__ out_final)         // [B][H/2]   packed or null
{
    constexpr int K    = H;
    constexpr int JC   = H / 8;
    constexpr int GR   = 4 * JC;
    constexpr int KT   = (K / 16) / KH;
    constexpr int MG   = (GR / 16) / MPW;
    static_assert(MG * KH == 16, "16 warps");
    constexpr int HLS2 = K / 2 + 4;        // uint2 stride per b row
    constexpr int SG   = 18;               // gsm stride (16 batch + pad)
    constexpr int HB   = 16;               // half-batch
    constexpr int HSLOT = HB * HLS2;       // uint2 per (half, slot)
    constexpr int GSM_H = KH * GR * SG;    // floats per half

    extern __shared__ char smraw[];
    uint2* hl  = reinterpret_cast<uint2*>(smraw);   // [half*2+slot][HB][HLS2]
    float* gsm = reinterpret_cast<float*>(smraw + (size_t)4 * HSLOT * 8); // [2][GSM_H]

    const int tid = threadIdx.x, wid = tid >> 5, lane = tid & 31;
    const int gid = lane >> 2, tk = lane & 3;
    const uint32_t r = cl_rank();
    const int b0 = (blockIdx.x >> 3) * 32;

    const int mg = wid / KH, kh = wid % KH;

    // ---- preload Whh fragments (bf16 hi/lo in registers) ------------------
    uint32_t Ahi[MPW][KT][4], Alo[MPW][KT][4];
    #pragma unroll
    for (int mp = 0; mp < MPW; ++mp) {
        int m0 = (mg * MPW + mp) * 16;
        int j1 = m0 + gid, j2 = j1 + 8;
        const float* w1 = Whh + (size_t)((j1 / JC) * H + r * JC + (j1 % JC)) * K;
        const float* w2 = Whh + (size_t)((j2 / JC) * H + r * JC + (j2 % JC)) * K;
        #pragma unroll
        for (int kt = 0; kt < KT; ++kt) {
            int ka = (kh * KT + kt) * 16 + 2 * tk;
            split_pack(w1[ka],     w1[ka + 1], Ahi[mp][kt][0], Alo[mp][kt][0]);
            split_pack(w2[ka],     w2[ka + 1], Ahi[mp][kt][1], Alo[mp][kt][1]);
            split_pack(w1[ka + 8], w1[ka + 9], Ahi[mp][kt][2], Alo[mp][kt][2]);
            split_pack(w2[ka + 8], w2[ka + 9], Ahi[mp][kt][3], Alo[mp][kt][3]);
        }
    }
    // zero all four h slots
    for (int i = tid; i < 4 * HSLOT * 2; i += 512)
        reinterpret_cast<uint32_t*>(hl)[i] = 0u;
    __syncthreads();
    CLUSTER_SYNC_();

    // ---- phase-2 identity --------------------------------------------------
    constexpr int ITh = HB * (JC / 2);
    const bool isB = tid >= 256;
    const int  lt  = isB ? tid - 256 : tid;
    const bool act = lt < ITh;
    const int  pbl = lt / (JC / 2);
    const int  kl  = lt % (JC / 2);
    const int  k0  = r * JC + 2 * kl;
    const int  kpg = (r * JC) / 2 + kl;
    const int  gb  = b0 + (isB ? 16 : 0) + pbl;     // global batch index
    const uint32_t sbase = smem_u32(smraw);
    float cv0 = 0.0f, cv1 = 0.0f;
    float2 xr[4];
    if (act) {
        const float* xgt = xg + (size_t)gb * xg_bs;  // t = 0
        #pragma unroll
        for (int g = 0; g < 4; ++g)
            xr[g] = *reinterpret_cast<const float2*>(xgt + g * H + k0);
    }

    // ---- phase 1: bf16 MMAs for one half -----------------------------------
    auto P1 = [&](int halfidx, int slot, float* gso) {
        const uint2* hb = hl + (size_t)(halfidx * 2 + slot) * HSLOT;
        float4 C[MPW][2];
        #pragma unroll
        for (int mp = 0; mp < MPW; ++mp)
            #pragma unroll
            for (int nt = 0; nt < 2; ++nt) C[mp][nt] = make_float4(0.f, 0.f, 0.f, 0.f);
        #pragma unroll
        for (int kt = 0; kt < KT; ++kt) {
            int kp0 = (kh * KT + kt) * 8 + tk;
            #pragma unroll
            for (int nt = 0; nt < 2; ++nt) {
                int n = nt * 8 + gid;
                uint2 u0 = hb[n * HLS2 + kp0];
                uint2 u1 = hb[n * HLS2 + kp0 + 4];
                #pragma unroll
                for (int mp = 0; mp < MPW; ++mp) {
                    mma_bf16(C[mp][nt], Ahi[mp][kt], u0.x, u1.x);
                    mma_bf16(C[mp][nt], Ahi[mp][kt], u0.y, u1.y);
                    mma_bf16(C[mp][nt], Alo[mp][kt], u0.x, u1.x);
                }
            }
        }
        float* gout = gso + kh * (GR * SG);
        #pragma unroll
        for (int mp = 0; mp < MPW; ++mp) {
            int m0 = (mg * MPW + mp) * 16;
            #pragma unroll
            for (int nt = 0; nt < 2; ++nt) {
                int col = nt * 8 + 2 * tk;
                *reinterpret_cast<float2*>(&gout[(m0 + gid) * SG + col]) =
                    make_float2(C[mp][nt].x, C[mp][nt].y);
                *reinterpret_cast<float2*>(&gout[(m0 + gid + 8) * SG + col]) =
                    make_float2(C[mp][nt].z, C[mp][nt].w);
            }
        }
    };

    // ---- phase 2: gates + state + packed broadcast + xg prefetch -----------
    auto P2 = [&](int t, int halfidx) {
        const float* gp0 = gsm + halfidx * GSM_H;
        float s0[4], s1[4];
        #pragma unroll
        for (int g = 0; g < 4; ++g) {
            float a0 = xr[g].x, a1 = xr[g].y;
            int row = (g * JC + 2 * kl) * SG + pbl;
            #pragma unroll
            for (int khx = 0; khx < KH; ++khx) {
                const float* gp = gp0 + khx * (GR * SG);
                a0 += gp[row];
                a1 += gp[row + SG];
            }
            s0[g] = a0; s1[g] = a1;
        }
        float i0 = sigf(s0[0]), i1 = sigf(s1[0]);
        float f0 = sigf(s0[1]), f1 = sigf(s1[1]);
        float g0 = tanhe(s0[2]), g1 = tanhe(s1[2]);
        float o0 = sigf(s0[3]), o1 = sigf(s1[3]);
        cv0 = f0 * cv0 + i0 * g0;
        cv1 = f1 * cv1 + i1 * g1;
        float h0v = o0 * tanhe(cv0);
        float h1v = o1 * tanhe(cv1);

        uint32_t hi2, lo2;
        split_pack(h0v, h1v, hi2, lo2);

        // broadcast first (drain overlaps the following P1)
        uint32_t fo = sbase +
            (uint32_t)((((halfidx * 2 + ((t + 1) & 1)) * HB + pbl) * HLS2 + kpg) * 8);
        #pragma unroll
        for (int p = 0; p < 8; ++p) {
            uint32_t ra = mapa_u32(fo, (uint32_t)p);
            st_cluster_v2(ra, hi2, lo2);
        }

        if (out_seq)
            out_seq[((size_t)gb * TT + t) * (H / 2) + kpg] = make_uint2(hi2, lo2);
        if (out_final && t == TT - 1)
            out_final[(size_t)gb * (H / 2) + kpg] = make_uint2(hi2, lo2);

        // prefetch xg for t+1 (consumed two brackets later)
        int tn = (t + 1 < TT) ? t + 1 : t;
        const float* xgt = xg + (size_t)tn * xg_ts + (size_t)gb * xg_bs;
        #pragma unroll
        for (int g = 0; g < 4; ++g)
            xr[g] = *reinterpret_cast<const float2*>(xgt + g * H + k0);
    };

    // ---- prologue: P1(A, 0) -------------------------------------------------
    P1(0, 0, gsm);
    __syncthreads();

    for (int t = 0; t < TT; ++t) {
        // bracket even: P2(A,t) || P1(B,t)
        if (!isB && act) P2(t, 0);
        P1(1, t & 1, gsm + GSM_H);
        CLUSTER_SYNC_();
        // bracket odd: P2(B,t) || P1(A,t+1)
        if (isB && act) P2(t, 1);
        if (t + 1 < TT) P1(0, (t + 1) & 1, gsm);
        CLUSTER_SYNC_();
    }
}

// ---------------------------------------------------------------------------
// Elementwise pack: fp32 pairs -> {bf16 hi x2, bf16 lo x2} uint2
// ---------------------------------------------------------------------------
__global__ __launch_bounds__(256) void pack_hilo_kernel(
    const float* __restrict__ src, uint2* __restrict__ dst, int npairs)
{
    int i = blockIdx.x * 256 + threadIdx.x;
    if (i >= npairs) return;
    float2 f = reinterpret_cast<const float2*>(src)[i];
    uint32_t h2, l2;
    split_pack(f.x, f.y, h2, l2);
    dst[i] = make_uint2(h2, l2);
}

// ---------------------------------------------------------------------------
// Tensor-core GEMM, PRE-PACKED bf16 hi/lo operands (no in-loop conversion):
//   C[m][n] = sum_k A[m][k]*B[n][k] + b1[n] (+ b2[n]), fp32-accurate
// BM=128 BN=64 BK=32 (16 pairs); 256 threads = 8 warps (4m x 2n), 2 CTAs/SM.
// ---------------------------------------------------------------------------
__global__ __launch_bounds__(256, 2) void hgemm_pk(
    const uint2* __restrict__ Apk,   // [M][Kp]
    const uint2* __restrict__ Bpk,   // [N][Kp]
    const float* __restrict__ b1, const float* __restrict__ b2,
    float* __restrict__ C, int M, int N, int Kp)
{
    __shared__ uint2 As[128][18];
    __shared__ uint2 Bs[64][18];

    const int tid = threadIdx.x, wid = tid >> 5, lane = tid & 31;
    const int gid = lane >> 2, tk = lane & 3;
    const int bm = blockIdx.y * 128;
    const int bn = blockIdx.x * 64;
    const int wm = (wid & 3) * 32;
    const int wn = (wid >> 2) * 32;

    float4 Cc[2][4];
    #pragma unroll
    for (int mp = 0; mp < 2; ++mp)
        #pragma unroll
        for (int nt = 0; nt < 4; ++nt) Cc[mp][nt] = make_float4(0.f, 0.f, 0.f, 0.f);

    const int arow = tid >> 1, ac = (tid & 1) * 8;
    const int brow = tid >> 2, bc = (tid & 3) * 4;
    const uint2* Ap = Apk + (size_t)(bm + arow) * Kp + ac;
    const uint2* Bp = Bpk + (size_t)(bn + brow) * Kp + bc;

    for (int kb = 0; kb < Kp; kb += 16) {
        #pragma unroll
        for (int v = 0; v < 4; ++v) {
            uint4 w = *reinterpret_cast<const uint4*>(Ap + kb + 2 * v);
            As[arow][ac + 2 * v]     = make_uint2(w.x, w.y);
            As[arow][ac + 2 * v + 1] = make_uint2(w.z, w.w);
        }
        #pragma unroll
        for (int v = 0; v < 2; ++v) {
            uint4 w = *reinterpret_cast<const uint4*>(Bp + kb + 2 * v);
            Bs[brow][bc + 2 * v]     = make_uint2(w.x, w.y);
            Bs[brow][bc + 2 * v + 1] = make_uint2(w.z, w.w);
        }
        __syncthreads();

        #pragma unroll
        for (int kt = 0; kt < 2; ++kt) {
            int kp = kt * 8 + tk;
            uint32_t Ah[2][4], Al[2][4];
            #pragma unroll
            for (int mp = 0; mp < 2; ++mp) {
                int r1 = wm + mp * 16 + gid;
                uint2 u00 = As[r1][kp],     u01 = As[r1][kp + 4];
                uint2 u10 = As[r1 + 8][kp], u11 = As[r1 + 8][kp + 4];
                Ah[mp][0] = u00.x; Ah[mp][1] = u10.x; Ah[mp][2] = u01.x; Ah[mp][3] = u11.x;
                Al[mp][0] = u00.y; Al[mp][1] = u10.y; Al[mp][2] = u01.y; Al[mp][3] = u11.y;
            }
            #pragma unroll
            for (int nt = 0; nt < 4; ++nt) {
                int n = wn + nt * 8 + gid;
                uint2 u0 = Bs[n][kp];
                uint2 u1 = Bs[n][kp + 4];
                #pragma unroll
                for (int mp = 0; mp < 2; ++mp) {
                    mma_bf16(Cc[mp][nt], Ah[mp], u0.x, u1.x);
                    mma_bf16(Cc[mp][nt], Ah[mp], u0.y, u1.y);
                    mma_bf16(Cc[mp][nt], Al[mp], u0.x, u1.x);
                }
            }
        }
        __syncthreads();
    }

    #pragma unroll
    for (int nt = 0; nt < 4; ++nt) {
        int n = bn + wn + nt * 8 + 2 * tk;
        float bb0 = b1[n]     + (b2 ? b2[n]     : 0.0f);
        float bb1 = b1[n + 1] + (b2 ? b2[n + 1] : 0.0f);
        #pragma unroll
        for (int mp = 0; mp < 2; ++mp) {
            int m1 = bm + wm + mp * 16 + gid;
            *reinterpret_cast<float2*>(C + (size_t)m1 * N + n) =
                make_float2(Cc[mp][nt].x + bb0, Cc[mp][nt].y + bb1);
            *reinterpret_cast<float2*>(C + (size_t)(m1 + 8) * N + n) =
                make_float2(Cc[mp][nt].z + bb0, Cc[mp][nt].w + bb1);
        }
    }
}

// ---------------------------------------------------------------------------
// Launch
// ---------------------------------------------------------------------------
// enc: h = 4*16*132*8 = 67584 ; gsm = 2*4*128*18*4 = 73728  -> 141312
static const int SMEM_ENC = 141312;
// dec: h = 4*16*68*8  = 34816 ; gsm = 2*4*64*18*4  = 36864  -> 71680
static const int SMEM_DEC = 71680;

static inline int cdiv(int a, int b) { return (a + b - 1) / b; }

extern "C" void kernel_launch(void* const* d_in, const int* in_sizes, int n_in,
                              void* d_out, int out_size)
{
    (void)in_sizes; (void)n_in; (void)out_size;
    const float* x        = (const float*)d_in[0];
    const float* e0_Wih   = (const float*)d_in[1];
    const float* e0_Whh   = (const float*)d_in[2];
    const float* e0_bih   = (const float*)d_in[3];
    const float* e0_bhh   = (const float*)d_in[4];
    const float* e1_Wih   = (const float*)d_in[5];
    const float* e1_Whh   = (const float*)d_in[6];
    const float* e1_bih   = (const float*)d_in[7];
    const float* e1_bhh   = (const float*)d_in[8];
    const float* d0_Wih   = (const float*)d_in[9];
    const float* d0_Whh   = (const float*)d_in[10];
    const float* d0_bih   = (const float*)d_in[11];
    const float* d0_bhh   = (const float*)d_in[12];
    const float* d1_Wih   = (const float*)d_in[13];
    const float* d1_Whh   = (const float*)d_in[14];
    const float* d1_bih   = (const float*)d_in[15];
    const float* d1_bhh   = (const float*)d_in[16];
    const float* out_W    = (const float*)d_in[17];
    const float* out_b    = (const float*)d_in[18];
    float* out = (float*)d_out;

    float *xg, *xgd0;
    uint2 *pk, *wpk, *hTpk;
    cudaGetSymbolAddress((void**)&xg,   g_xg);
    cudaGetSymbolAddress((void**)&pk,   g_pk);
    cudaGetSymbolAddress((void**)&wpk,  g_wpk);
    cudaGetSymbolAddress((void**)&hTpk, g_hTpk);
    cudaGetSymbolAddress((void**)&xgd0, g_xgd0);

    cudaFuncSetAttribute(lstm_rec_pipe<DHID, 4, 2>,
                         cudaFuncAttributeMaxDynamicSharedMemorySize, SMEM_ENC);
    cudaFuncSetAttribute(lstm_rec_pipe<DIN, 4, 1>,
                         cudaFuncAttributeMaxDynamicSharedMemorySize, SMEM_DEC);

    const int MT = BB * TT;  // 65536

    // 1) pack x -> pk ; pack e0_Wih ; xg0 = x @ e0_Wih^T + b
    {
        int np = MT * DIN / 2;
        pack_hilo_kernel<<<cdiv(np, 256), 256>>>(x, pk, np);
        int nw = 4 * DHID * DIN / 2;
        pack_hilo_kernel<<<cdiv(nw, 256), 256>>>(e0_Wih, wpk, nw);
        hgemm_pk<<<dim3(4 * DHID / 64, MT / 128), 256>>>(
            pk, wpk, e0_bih, e0_bhh, xg, MT, 4 * DHID, DIN / 2);
    }
    // 2) enc0 recurrence -> e0 packed (pk)
    lstm_rec_pipe<DHID, 4, 2><<<128, 512, SMEM_ENC>>>(
        e0_Whh, xg, (size_t)TT * 4 * DHID, 4 * DHID, pk, nullptr);

    // 3) pack e1_Wih ; xg1 = e0 @ e1_Wih^T + b
    {
        int nw = 4 * DHID * DHID / 2;
        pack_hilo_kernel<<<cdiv(nw, 256), 256>>>(e1_Wih, wpk, nw);
        hgemm_pk<<<dim3(4 * DHID / 64, MT / 128), 256>>>(
            pk, wpk, e1_bih, e1_bhh, xg, MT, 4 * DHID, DHID / 2);
    }
    // 4) enc1 recurrence -> hT packed
    lstm_rec_pipe<DHID, 4, 2><<<128, 512, SMEM_ENC>>>(
        e1_Whh, xg, (size_t)TT * 4 * DHID, 4 * DHID, nullptr, hTpk);

    // 5) pack d0_Wih ; xgd0 = hT @ d0_Wih^T + b  [512, 512]
    {
        int nw = 4 * DIN * DHID / 2;
        pack_hilo_kernel<<<cdiv(nw, 256), 256>>>(d0_Wih, wpk, nw);
        hgemm_pk<<<dim3(4 * DIN / 64, BB / 128), 256>>>(
            hTpk, wpk, d0_bih, d0_bhh, xgd0, BB, 4 * DIN, DHID / 2);
    }
    // 6) dec0 recurrence (t-stride 0) -> d0 packed (pk)
    lstm_rec_pipe<DIN, 4, 1><<<128, 512, SMEM_DEC>>>(
        d0_Whh, xgd0, (size_t)4 * DIN, 0, pk, nullptr);

    // 7) pack d1_Wih ; xgd1 = d0 @ d1_Wih^T + b
    {
        int nw = 4 * DIN * DIN / 2;
        pack_hilo_kernel<<<cdiv(nw, 256), 256>>>(d1_Wih, wpk, nw);
        hgemm_pk<<<dim3(4 * DIN / 64, MT / 128), 256>>>(
            pk, wpk, d1_bih, d1_bhh, xg, MT, 4 * DIN, DIN / 2);
    }
    // 8) dec1 recurrence -> d1 packed (pk)
    lstm_rec_pipe<DIN, 4, 1><<<128, 512, SMEM_DEC>>>(
        d1_Whh, xg, (size_t)TT * 4 * DIN, 4 * DIN, pk, nullptr);

    // 9) pack out_W ; out = d1 @ out_W^T + out_b
    {
        int nw = DIN * DIN / 2;
        pack_hilo_kernel<<<cdiv(nw, 256), 256>>>(out_W, wpk, nw);
        hgemm_pk<<<dim3(DIN / 64, MT / 128), 256>>>(
            pk, wpk, out_b, nullptr, out, MT, DIN, DIN / 2);
    }
}

// round 9
// speedup vs baseline: 3.0242x; 1.4260x over previous
#include <cuda_runtime.h>
#include <cuda_bf16.h>
#include <cstdint>
#include <cstddef>

#define BB   512
#define TT   128
#define DIN  128
#define DHID 256

// ---------------------------------------------------------------------------
// Scratch (device globals; no allocations allowed)
// ---------------------------------------------------------------------------
__device__ float g_xg  [(size_t)BB * TT * 4 * DHID];   // fp32 gate pre-activations
__device__ uint2 g_pk  [(size_t)BB * TT * DHID / 2];   // packed hi/lo activations
__device__ uint2 g_wpk [(size_t)4 * DHID * DHID / 2];  // packed weights (reused)
__device__ uint2 g_hTpk[(size_t)BB * DHID / 2];        // packed hT
__device__ float g_xgd0[(size_t)BB * 4 * DIN];         // dec0 xg (constant over t)

// ---------------------------------------------------------------------------
// Helpers
// ---------------------------------------------------------------------------
__device__ __forceinline__ float sigf(float x) { return 1.0f / (1.0f + __expf(-x)); }
__device__ __forceinline__ float tanhe(float x) {
    x = fminf(fmaxf(x, -15.0f), 15.0f);
    float e = __expf(-2.0f * x);
    return __fdividef(1.0f - e, 1.0f + e);
}
__device__ __forceinline__ uint32_t pack_bf16x2(float a, float b) {
    uint32_t r; asm("cvt.rn.bf16x2.f32 %0, %1, %2;" : "=r"(r) : "f"(b), "f"(a)); return r;
}
__device__ __forceinline__ void split_pack(float f0, float f1,
                                           uint32_t& hi2, uint32_t& lo2) {
    float h0 = __bfloat162float(__float2bfloat16(f0));
    float h1 = __bfloat162float(__float2bfloat16(f1));
    hi2 = pack_bf16x2(h0, h1);
    lo2 = pack_bf16x2(f0 - h0, f1 - h1);
}
__device__ __forceinline__ uint32_t smem_u32(const void* p) {
    uint32_t a;
    asm("{ .reg .u64 t; cvta.to.shared.u64 t, %1; cvt.u32.u64 %0, t; }" : "=r"(a) : "l"(p));
    return a;
}
__device__ __forceinline__ uint32_t cl_rank() {
    uint32_t r; asm("mov.u32 %0, %%cluster_ctarank;" : "=r"(r)); return r;
}
__device__ __forceinline__ uint32_t mapa_u32(uint32_t addr, uint32_t rank) {
    uint32_t r;
    asm("mapa.shared::cluster.u32 %0, %1, %2;" : "=r"(r) : "r"(addr), "r"(rank));
    return r;
}
#define CLUSTER_SYNC_() do { \
    asm volatile("barrier.cluster.arrive.aligned;" ::: "memory"); \
    asm volatile("barrier.cluster.wait.aligned;"   ::: "memory"); \
} while (0)

__device__ __forceinline__ void mb_init(uint32_t mb, uint32_t cnt) {
    asm volatile("mbarrier.init.shared.b64 [%0], %1;" :: "r"(mb), "r"(cnt) : "memory");
}
__device__ __forceinline__ void mb_arrive_tx(uint32_t mb, uint32_t tx) {
    asm volatile("mbarrier.arrive.expect_tx.shared.b64 _, [%0], %1;"
                 :: "r"(mb), "r"(tx) : "memory");
}
__device__ __forceinline__ void mb_wait(uint32_t mb, uint32_t parity) {
    asm volatile(
        "{\n\t.reg .pred P;\n\t"
        "WL_%=:\n\t"
        "mbarrier.try_wait.parity.acquire.cluster.shared::cta.b64 P, [%0], %1, 0x989680;\n\t"
        "@P bra.uni WD_%=;\n\t"
        "bra.uni WL_%=;\n\t"
        "WD_%=:\n\t}"
        :: "r"(mb), "r"(parity) : "memory");
}
// async store to (possibly remote) CTA smem, signaling its mbarrier tx count
__device__ __forceinline__ void st_async_v2(uint32_t raddr, uint32_t rmbar,
                                            uint32_t a, uint32_t b) {
    asm volatile(
        "st.async.shared::cluster.mbarrier::complete_tx::bytes.v2.b32 [%0], {%2,%3}, [%1];"
        :: "r"(raddr), "r"(rmbar), "r"(a), "r"(b) : "memory");
}

__device__ __forceinline__ void mma_bf16(float4& c, const uint32_t a[4],
                                         uint32_t b0, uint32_t b1) {
    asm volatile(
        "mma.sync.aligned.m16n8k16.row.col.f32.bf16.bf16.f32 "
        "{%0,%1,%2,%3}, {%4,%5,%6,%7}, {%8,%9}, {%0,%1,%2,%3};"
        : "+f"(c.x), "+f"(c.y), "+f"(c.z), "+f"(c.w)
        : "r"(a[0]), "r"(a[1]), "r"(a[2]), "r"(a[3]), "r"(b0), "r"(b1));
}

// ---------------------------------------------------------------------------
// Recurrent LSTM body: bf16 hi/lo tensor cores, two-half pipeline,
// st.async + mbarrier-tx h exchange (NO per-step cluster barriers).
// CL CTAs per cluster share one batch-tile of Bt=4*CL rows; rank r owns gate
// rows {g*H + r*JC + cl}. Whh in registers (bf16 hi + residual lo).
// h exchanged as packed uint2 {hi bf16x2, lo bf16x2} per k-pair via st.async;
// consumer CTA waits on its own mbarrier reaching HB*(H/2)*8 bytes.
// Timestep = 2 brackets: [P2(A,t);P1(B,t);bar][P2(B,t);P1(A,t+1);bar].
// ---------------------------------------------------------------------------
template <int H, int CL, int KH, int MPW>
__device__ __forceinline__ void lstm_body(
    const float* __restrict__ Whh, const float* __restrict__ xg,
    size_t xg_bs, int xg_ts,
    uint2* __restrict__ out_seq, uint2* __restrict__ out_final)
{
    constexpr int K    = H;
    constexpr int JC   = H / CL;
    constexpr int GR   = 4 * H / CL;
    constexpr int KT   = (K / 16) / KH;
    constexpr int MG   = (GR / 16) / MPW;
    static_assert(MG * KH == 16, "16 warps");
    constexpr int Bt   = 4 * CL;
    constexpr int HB   = Bt / 2;            // half-batch
    constexpr int NT   = HB / 8;            // n8 tiles per half
    static_assert(NT >= 1, "NT");
    constexpr int HLS2 = K / 2 + 4;         // uint2 stride per b row
    static_assert(HLS2 % 16 == 4, "banks");
    constexpr int SG   = HB + 2;
    constexpr int HSLOT = HB * HLS2;        // uint2 per (half,slot)
    constexpr int GSM_H = KH * GR * SG;
    constexpr uint32_t TXB = (uint32_t)HB * (K / 2) * 8;  // bytes per mbar phase
    constexpr int HL_OFF = 32;              // mbar block at smem start

    extern __shared__ char smraw[];
    uint2* hl  = reinterpret_cast<uint2*>(smraw + HL_OFF);            // [4][HB][HLS2]
    float* gsm = reinterpret_cast<float*>(smraw + HL_OFF + (size_t)4 * HSLOT * 8);

    const int tid = threadIdx.x, wid = tid >> 5, lane = tid & 31;
    const int gid = lane >> 2, tk = lane & 3;
    const uint32_t r = cl_rank();
    const int b0 = (blockIdx.x / CL) * Bt;
    const uint32_t sbase = smem_u32(smraw);

    const int mg = wid / KH, kh = wid % KH;

    // ---- preload Whh fragments -------------------------------------------
    uint32_t Ahi[MPW][KT][4], Alo[MPW][KT][4];
    #pragma unroll
    for (int mp = 0; mp < MPW; ++mp) {
        int m0 = (mg * MPW + mp) * 16;
        int j1 = m0 + gid, j2 = j1 + 8;
        const float* w1 = Whh + (size_t)((j1 / JC) * H + r * JC + (j1 % JC)) * K;
        const float* w2 = Whh + (size_t)((j2 / JC) * H + r * JC + (j2 % JC)) * K;
        #pragma unroll
        for (int kt = 0; kt < KT; ++kt) {
            int ka = (kh * KT + kt) * 16 + 2 * tk;
            split_pack(w1[ka],     w1[ka + 1], Ahi[mp][kt][0], Alo[mp][kt][0]);
            split_pack(w2[ka],     w2[ka + 1], Ahi[mp][kt][1], Alo[mp][kt][1]);
            split_pack(w1[ka + 8], w1[ka + 9], Ahi[mp][kt][2], Alo[mp][kt][2]);
            split_pack(w2[ka + 8], w2[ka + 9], Ahi[mp][kt][3], Alo[mp][kt][3]);
        }
    }
    // ---- init mbarriers + arm phase 0, zero h slots ------------------------
    if (tid == 0) {
        #pragma unroll
        for (int i = 0; i < 4; ++i) {
            mb_init(sbase + i * 8, 1);
            mb_arrive_tx(sbase + i * 8, TXB);
        }
    }
    for (int i = tid; i < 4 * HSLOT * 2; i += 512)
        reinterpret_cast<uint32_t*>(hl)[i] = 0u;
    __syncthreads();
    CLUSTER_SYNC_();          // all mbarriers live before any st.async

    // peer smem bases
    uint32_t pbase[CL];
    #pragma unroll
    for (int p = 0; p < CL; ++p) pbase[p] = mapa_u32(sbase, (uint32_t)p);

    // ---- phase-2 identity ---------------------------------------------------
    constexpr int ITh = HB * (JC / 2);
    static_assert(ITh <= 256, "P2 items fit half the threads");
    const bool isB = tid >= 256;
    const int  lt  = isB ? tid - 256 : tid;
    const bool act = lt < ITh;
    const int  pbl = lt / (JC / 2);
    const int  kl  = lt % (JC / 2);
    const int  k0  = r * JC + 2 * kl;
    const int  kpg = (r * JC) / 2 + kl;
    const int  gb  = b0 + (isB ? HB : 0) + pbl;
    float cv0 = 0.0f, cv1 = 0.0f;
    uint32_t phbits = 0;     // per-mbar phase parity
    float2 xr[4];
    if (act) {
        const float* xgt = xg + (size_t)gb * xg_bs;   // t = 0
        #pragma unroll
        for (int g = 0; g < 4; ++g)
            xr[g] = *reinterpret_cast<const float2*>(xgt + g * H + k0);
    }

    // ---- P1: bf16 MMAs for one (half, slot) --------------------------------
    auto P1 = [&](int halfidx, int slot, float* gso, bool dowait) {
        const int idx = halfidx * 2 + slot;
        if (dowait) {
            uint32_t mb = sbase + idx * 8;
            mb_wait(mb, (phbits >> idx) & 1u);
            phbits ^= (1u << idx);
            if (tid == 0) mb_arrive_tx(mb, TXB);   // re-arm next phase
        }
        const uint2* hb = hl + (size_t)idx * HSLOT;
        float4 C[MPW][NT];
        #pragma unroll
        for (int mp = 0; mp < MPW; ++mp)
            #pragma unroll
            for (int nt = 0; nt < NT; ++nt) C[mp][nt] = make_float4(0.f, 0.f, 0.f, 0.f);
        #pragma unroll
        for (int kt = 0; kt < KT; ++kt) {
            int kp0 = (kh * KT + kt) * 8 + tk;
            #pragma unroll
            for (int nt = 0; nt < NT; ++nt) {
                int n = nt * 8 + gid;
                uint2 u0 = hb[n * HLS2 + kp0];
                uint2 u1 = hb[n * HLS2 + kp0 + 4];
                #pragma unroll
                for (int mp = 0; mp < MPW; ++mp) {
                    mma_bf16(C[mp][nt], Ahi[mp][kt], u0.x, u1.x);
                    mma_bf16(C[mp][nt], Ahi[mp][kt], u0.y, u1.y);
                    mma_bf16(C[mp][nt], Alo[mp][kt], u0.x, u1.x);
                }
            }
        }
        float* gout = gso + kh * (GR * SG);
        #pragma unroll
        for (int mp = 0; mp < MPW; ++mp) {
            int m0 = (mg * MPW + mp) * 16;
            #pragma unroll
            for (int nt = 0; nt < NT; ++nt) {
                int col = nt * 8 + 2 * tk;
                *reinterpret_cast<float2*>(&gout[(m0 + gid) * SG + col]) =
                    make_float2(C[mp][nt].x, C[mp][nt].y);
                *reinterpret_cast<float2*>(&gout[(m0 + gid + 8) * SG + col]) =
                    make_float2(C[mp][nt].z, C[mp][nt].w);
            }
        }
    };

    // ---- P2: gates + state + st.async broadcast + xg prefetch --------------
    auto P2 = [&](int t, int halfidx) {
        const float* gp0 = gsm + halfidx * GSM_H;
        float s0[4], s1[4];
        #pragma unroll
        for (int g = 0; g < 4; ++g) {
            float a0 = xr[g].x, a1 = xr[g].y;
            int row = (g * JC + 2 * kl) * SG + pbl;
            #pragma unroll
            for (int khx = 0; khx < KH; ++khx) {
                const float* gp = gp0 + khx * (GR * SG);
                a0 += gp[row];
                a1 += gp[row + SG];
            }
            s0[g] = a0; s1[g] = a1;
        }
        float i0 = sigf(s0[0]), i1 = sigf(s1[0]);
        float f0 = sigf(s0[1]), f1 = sigf(s1[1]);
        float g0 = tanhe(s0[2]), g1 = tanhe(s1[2]);
        float o0 = sigf(s0[3]), o1 = sigf(s1[3]);
        cv0 = f0 * cv0 + i0 * g0;
        cv1 = f1 * cv1 + i1 * g1;
        float h0v = o0 * tanhe(cv0);
        float h1v = o1 * tanhe(cv1);

        uint32_t hi2, lo2;
        split_pack(h0v, h1v, hi2, lo2);

        if (t + 1 < TT) {   // broadcast (skipped on last step: nothing consumes it)
            const int idx = halfidx * 2 + ((t + 1) & 1);
            uint32_t off_mb  = (uint32_t)idx * 8;
            uint32_t off_dat = HL_OFF +
                (uint32_t)(((idx * HB + pbl) * HLS2 + kpg) * 8);
            #pragma unroll
            for (int p = 0; p < CL; ++p)
                st_async_v2(pbase[p] + off_dat, pbase[p] + off_mb, hi2, lo2);
        }

        if (out_seq)
            out_seq[((size_t)gb * TT + t) * (H / 2) + kpg] = make_uint2(hi2, lo2);
        if (out_final && t == TT - 1)
            out_final[(size_t)gb * (H / 2) + kpg] = make_uint2(hi2, lo2);

        int tn = (t + 1 < TT) ? t + 1 : t;
        const float* xgt = xg + (size_t)tn * xg_ts + (size_t)gb * xg_bs;
        #pragma unroll
        for (int g = 0; g < 4; ++g)
            xr[g] = *reinterpret_cast<const float2*>(xgt + g * H + k0);
    };

    // ---- prologue + main loop ----------------------------------------------
    P1(0, 0, gsm, false);          // h(0)=0, slot prefilled
    __syncthreads();

    for (int t = 0; t < TT; ++t) {
        // even bracket: P2(A,t) || P1(B, t&1)
        if (!isB && act) P2(t, 0);
        P1(1, t & 1, gsm + GSM_H, t > 0);
        __syncthreads();
        // odd bracket: P2(B,t) || P1(A, (t+1)&1)
        if (isB && act) P2(t, 1);
        if (t + 1 < TT) P1(0, (t + 1) & 1, gsm, true);
        __syncthreads();
    }
    CLUSTER_SYNC_();   // keep peer smem alive until everyone is done
}

// enc: H=256, CL=8, KH=4, MPW=2   dec: H=128, CL=4, KH=2, MPW=1
__global__ void __cluster_dims__(8, 1, 1) __launch_bounds__(512, 1)
lstm_enc(const float* __restrict__ Whh, const float* __restrict__ xg,
         size_t xg_bs, int xg_ts, uint2* __restrict__ out_seq,
         uint2* __restrict__ out_final)
{
    lstm_body<DHID, 8, 4, 2>(Whh, xg, xg_bs, xg_ts, out_seq, out_final);
}
__global__ void __cluster_dims__(4, 1, 1) __launch_bounds__(512, 1)
lstm_dec(const float* __restrict__ Whh, const float* __restrict__ xg,
         size_t xg_bs, int xg_ts, uint2* __restrict__ out_seq,
         uint2* __restrict__ out_final)
{
    lstm_body<DIN, 4, 2, 1>(Whh, xg, xg_bs, xg_ts, out_seq, out_final);
}

// ---------------------------------------------------------------------------
// Elementwise pack: fp32 pairs -> {bf16 hi x2, bf16 lo x2}
// ---------------------------------------------------------------------------
__global__ __launch_bounds__(256) void pack_hilo_kernel(
    const float* __restrict__ src, uint2* __restrict__ dst, int npairs)
{
    int i = blockIdx.x * 256 + threadIdx.x;
    if (i >= npairs) return;
    float2 f = reinterpret_cast<const float2*>(src)[i];
    uint32_t h2, l2;
    split_pack(f.x, f.y, h2, l2);
    dst[i] = make_uint2(h2, l2);
}

// ---------------------------------------------------------------------------
// Tensor-core GEMM, pre-packed bf16 hi/lo operands (proven in R7)
// ---------------------------------------------------------------------------
__global__ __launch_bounds__(256, 2) void hgemm_pk(
    const uint2* __restrict__ Apk, const uint2* __restrict__ Bpk,
    const float* __restrict__ b1, const float* __restrict__ b2,
    float* __restrict__ C, int M, int N, int Kp)
{
    __shared__ uint2 As[128][18];
    __shared__ uint2 Bs[64][18];

    const int tid = threadIdx.x, wid = tid >> 5, lane = tid & 31;
    const int gid = lane >> 2, tk = lane & 3;
    const int bm = blockIdx.y * 128;
    const int bn = blockIdx.x * 64;
    const int wm = (wid & 3) * 32;
    const int wn = (wid >> 2) * 32;

    float4 Cc[2][4];
    #pragma unroll
    for (int mp = 0; mp < 2; ++mp)
        #pragma unroll
        for (int nt = 0; nt < 4; ++nt) Cc[mp][nt] = make_float4(0.f, 0.f, 0.f, 0.f);

    const int arow = tid >> 1, ac = (tid & 1) * 8;
    const int brow = tid >> 2, bc = (tid & 3) * 4;
    const uint2* Ap = Apk + (size_t)(bm + arow) * Kp + ac;
    const uint2* Bp = Bpk + (size_t)(bn + brow) * Kp + bc;

    for (int kb = 0; kb < Kp; kb += 16) {
        #pragma unroll
        for (int v = 0; v < 4; ++v) {
            uint4 w = *reinterpret_cast<const uint4*>(Ap + kb + 2 * v);
            As[arow][ac + 2 * v]     = make_uint2(w.x, w.y);
            As[arow][ac + 2 * v + 1] = make_uint2(w.z, w.w);
        }
        #pragma unroll
        for (int v = 0; v < 2; ++v) {
            uint4 w = *reinterpret_cast<const uint4*>(Bp + kb + 2 * v);
            Bs[brow][bc + 2 * v]     = make_uint2(w.x, w.y);
            Bs[brow][bc + 2 * v + 1] = make_uint2(w.z, w.w);
        }
        __syncthreads();

        #pragma unroll
        for (int kt = 0; kt < 2; ++kt) {
            int kp = kt * 8 + tk;
            uint32_t Ah[2][4], Al[2][4];
            #pragma unroll
            for (int mp = 0; mp < 2; ++mp) {
                int r1 = wm + mp * 16 + gid;
                uint2 u00 = As[r1][kp],     u01 = As[r1][kp + 4];
                uint2 u10 = As[r1 + 8][kp], u11 = As[r1 + 8][kp + 4];
                Ah[mp][0] = u00.x; Ah[mp][1] = u10.x; Ah[mp][2] = u01.x; Ah[mp][3] = u11.x;
                Al[mp][0] = u00.y; Al[mp][1] = u10.y; Al[mp][2] = u01.y; Al[mp][3] = u11.y;
            }
            #pragma unroll
            for (int nt = 0; nt < 4; ++nt) {
                int n = wn + nt * 8 + gid;
                uint2 u0 = Bs[n][kp];
                uint2 u1 = Bs[n][kp + 4];
                #pragma unroll
                for (int mp = 0; mp < 2; ++mp) {
                    mma_bf16(Cc[mp][nt], Ah[mp], u0.x, u1.x);
                    mma_bf16(Cc[mp][nt], Ah[mp], u0.y, u1.y);
                    mma_bf16(Cc[mp][nt], Al[mp], u0.x, u1.x);
                }
            }
        }
        __syncthreads();
    }

    #pragma unroll
    for (int nt = 0; nt < 4; ++nt) {
        int n = bn + wn + nt * 8 + 2 * tk;
        float bb0 = b1[n]     + (b2 ? b2[n]     : 0.0f);
        float bb1 = b1[n + 1] + (b2 ? b2[n + 1] : 0.0f);
        #pragma unroll
        for (int mp = 0; mp < 2; ++mp) {
            int m1 = bm + wm + mp * 16 + gid;
            *reinterpret_cast<float2*>(C + (size_t)m1 * N + n) =
                make_float2(Cc[mp][nt].x + bb0, Cc[mp][nt].y + bb1);
            *reinterpret_cast<float2*>(C + (size_t)(m1 + 8) * N + n) =
                make_float2(Cc[mp][nt].z + bb0, Cc[mp][nt].w + bb1);
        }
    }
}

// ---------------------------------------------------------------------------
// Launch
// ---------------------------------------------------------------------------
// enc: 32 + 4*(16*132)*8 + 2*(4*128*18)*4 = 32+67584+73728 = 141344
static const int SMEM_ENC = 141344;
// dec: 32 + 4*(8*68)*8 + 2*(2*128*10)*4  = 32+17408+20480 =  37920
static const int SMEM_DEC = 37920;

static inline int cdiv(int a, int b) { return (a + b - 1) / b; }

extern "C" void kernel_launch(void* const* d_in, const int* in_sizes, int n_in,
                              void* d_out, int out_size)
{
    (void)in_sizes; (void)n_in; (void)out_size;
    const float* x        = (const float*)d_in[0];
    const float* e0_Wih   = (const float*)d_in[1];
    const float* e0_Whh   = (const float*)d_in[2];
    const float* e0_bih   = (const float*)d_in[3];
    const float* e0_bhh   = (const float*)d_in[4];
    const float* e1_Wih   = (const float*)d_in[5];
    const float* e1_Whh   = (const float*)d_in[6];
    const float* e1_bih   = (const float*)d_in[7];
    const float* e1_bhh   = (const float*)d_in[8];
    const float* d0_Wih   = (const float*)d_in[9];
    const float* d0_Whh   = (const float*)d_in[10];
    const float* d0_bih   = (const float*)d_in[11];
    const float* d0_bhh   = (const float*)d_in[12];
    const float* d1_Wih   = (const float*)d_in[13];
    const float* d1_Whh   = (const float*)d_in[14];
    const float* d1_bih   = (const float*)d_in[15];
    const float* d1_bhh   = (const float*)d_in[16];
    const float* out_W    = (const float*)d_in[17];
    const float* out_b    = (const float*)d_in[18];
    float* out = (float*)d_out;

    float *xg, *xgd0;
    uint2 *pk, *wpk, *hTpk;
    cudaGetSymbolAddress((void**)&xg,   g_xg);
    cudaGetSymbolAddress((void**)&pk,   g_pk);
    cudaGetSymbolAddress((void**)&wpk,  g_wpk);
    cudaGetSymbolAddress((void**)&hTpk, g_hTpk);
    cudaGetSymbolAddress((void**)&xgd0, g_xgd0);

    cudaFuncSetAttribute(lstm_enc,
                         cudaFuncAttributeMaxDynamicSharedMemorySize, SMEM_ENC);
    cudaFuncSetAttribute(lstm_dec,
                         cudaFuncAttributeMaxDynamicSharedMemorySize, SMEM_DEC);

    const int MT = BB * TT;  // 65536

    // 1) pack x, pack e0_Wih ; xg0 = x @ e0_Wih^T + b
    {
        int np = MT * DIN / 2;
        pack_hilo_kernel<<<cdiv(np, 256), 256>>>(x, pk, np);
        int nw = 4 * DHID * DIN / 2;
        pack_hilo_kernel<<<cdiv(nw, 256), 256>>>(e0_Wih, wpk, nw);
        hgemm_pk<<<dim3(4 * DHID / 64, MT / 128), 256>>>(
            pk, wpk, e0_bih, e0_bhh, xg, MT, 4 * DHID, DIN / 2);
    }
    // 2) enc0 recurrence -> e0 packed
    lstm_enc<<<128, 512, SMEM_ENC>>>(
        e0_Whh, xg, (size_t)TT * 4 * DHID, 4 * DHID, pk, nullptr);

    // 3) pack e1_Wih ; xg1 = e0 @ e1_Wih^T + b
    {
        int nw = 4 * DHID * DHID / 2;
        pack_hilo_kernel<<<cdiv(nw, 256), 256>>>(e1_Wih, wpk, nw);
        hgemm_pk<<<dim3(4 * DHID / 64, MT / 128), 256>>>(
            pk, wpk, e1_bih, e1_bhh, xg, MT, 4 * DHID, DHID / 2);
    }
    // 4) enc1 recurrence -> hT packed
    lstm_enc<<<128, 512, SMEM_ENC>>>(
        e1_Whh, xg, (size_t)TT * 4 * DHID, 4 * DHID, nullptr, hTpk);

    // 5) pack d0_Wih ; xgd0 = hT @ d0_Wih^T + b
    {
        int nw = 4 * DIN * DHID / 2;
        pack_hilo_kernel<<<cdiv(nw, 256), 256>>>(d0_Wih, wpk, nw);
        hgemm_pk<<<dim3(4 * DIN / 64, BB / 128), 256>>>(
            hTpk, wpk, d0_bih, d0_bhh, xgd0, BB, 4 * DIN, DHID / 2);
    }
    // 6) dec0 recurrence (t-stride 0) -> d0 packed
    lstm_dec<<<128, 512, SMEM_DEC>>>(
        d0_Whh, xgd0, (size_t)4 * DIN, 0, pk, nullptr);

    // 7) pack d1_Wih ; xgd1 = d0 @ d1_Wih^T + b
    {
        int nw = 4 * DIN * DIN / 2;
        pack_hilo_kernel<<<cdiv(nw, 256), 256>>>(d1_Wih, wpk, nw);
        hgemm_pk<<<dim3(4 * DIN / 64, MT / 128), 256>>>(
            pk, wpk, d1_bih, d1_bhh, xg, MT, 4 * DIN, DIN / 2);
    }
    // 8) dec1 recurrence -> d1 packed
    lstm_dec<<<128, 512, SMEM_DEC>>>(
        d1_Whh, xg, (size_t)TT * 4 * DIN, 4 * DIN, pk, nullptr);

    // 9) pack out_W ; out = d1 @ out_W^T + out_b
    {
        int nw = DIN * DIN / 2;
        pack_hilo_kernel<<<cdiv(nw, 256), 256>>>(out_W, wpk, nw);
        hgemm_pk<<<dim3(DIN / 64, MT / 128), 256>>>(
            pk, wpk, out_b, nullptr, out, MT, DIN, DIN / 2);
    }
}